// round 7
// baseline (speedup 1.0000x reference)
#include <cuda_runtime.h>
#include <cuda_fp16.h>
#include <math.h>
#include <stdint.h>

#define B_   8
#define T_   1024
#define D_   768
#define H_   12
#define WIN_ 768
#define M_   (B_*T_)   // 8192

// ---------------- scratch (static device globals) ---------------------------
__device__ __half g_x1h[M_ * D_];
__device__ __half g_qkvh[M_ * 3 * D_];
__device__ __half g_attnh[M_ * D_];
__device__ float  g_x2[M_ * D_];
__device__ __half g_hh[M_ * 4 * D_];
__device__ __half g_wah[D_ * 3 * D_];
__device__ __half g_wph[D_ * D_];
__device__ __half g_wfh[D_ * 4 * D_];
__device__ __half g_wfph[4 * D_ * D_];

// ---------------- helpers -----------------------------------------------------
__device__ __forceinline__ uint32_t smem_to_u32(const void* p) {
    uint32_t a;
    asm("{ .reg .u64 t; cvta.to.shared.u64 t, %1; cvt.u32.u64 %0, t; }" : "=r"(a) : "l"(p));
    return a;
}
__device__ __forceinline__ uint32_t h2u(__half2 v) { return *(uint32_t*)&v; }

#define CP16(saddr, gptr) \
    asm volatile("cp.async.cg.shared.global [%0], [%1], 16;" :: "r"(saddr), "l"(gptr))
#define CP_COMMIT() asm volatile("cp.async.commit_group;" ::: "memory")
#define CP_WAIT2()  asm volatile("cp.async.wait_group 2;" ::: "memory")

#define LDSM4(r0, r1, r2, r3, addr) \
    asm volatile("ldmatrix.sync.aligned.m8n8.x4.shared.b16 {%0,%1,%2,%3}, [%4];" \
        : "=r"(r0), "=r"(r1), "=r"(r2), "=r"(r3) : "r"(addr))
#define LDSM4T(r0, r1, r2, r3, addr) \
    asm volatile("ldmatrix.sync.aligned.m8n8.x4.trans.shared.b16 {%0,%1,%2,%3}, [%4];" \
        : "=r"(r0), "=r"(r1), "=r"(r2), "=r"(r3) : "r"(addr))

__device__ __forceinline__ void mma1616(float* d, const uint32_t* a, const uint32_t* b) {
    asm volatile(
        "mma.sync.aligned.m16n8k16.row.col.f32.f16.f16.f32 "
        "{%0,%1,%2,%3}, {%4,%5,%6,%7}, {%8,%9}, {%0,%1,%2,%3};"
        : "+f"(d[0]), "+f"(d[1]), "+f"(d[2]), "+f"(d[3])
        : "r"(a[0]), "r"(a[1]), "r"(a[2]), "r"(a[3]), "r"(b[0]), "r"(b[1]));
}

// ---------------- fp16 tensor-core GEMM ----------------------------------------
// C[M,N] = A[M,K] @ W[K,N] + bias (+res / gelu). A, W fp16; accum fp32.
// 128x128 tile, BK=32, 8 warps (64x32 each), 4-stage cp.async pipeline,
// single __syncthreads per K-iter, all fragments via ldmatrix.
enum { EPI_BIAS = 0, EPI_BIAS_RES = 1, EPI_BIAS_GELU = 2 };

#define NSTG 4
#define APADH 40
#define BPADH 136
#define A_ST (128 * APADH)
#define B_ST (32 * BPADH)
#define STG_H (A_ST + B_ST)
#define GEMM_SMEM (NSTG * STG_H * 2)    // 75776 bytes

template <int EPI, bool OUTH>
__global__ void __launch_bounds__(256, 2) hgemm(
    const __half* __restrict__ A, const __half* __restrict__ W,
    const float* __restrict__ bias, const float* __restrict__ R,
    float* __restrict__ Cf, __half* __restrict__ Ch, int N, int K)
{
    extern __shared__ char dynsm[];
    __half* smh = (__half*)dynsm;
    const int tid = threadIdx.x;
    const int wid = tid >> 5, lane = tid & 31;
    const int wm = wid >> 2, wn = wid & 3;
    const int bm = blockIdx.y << 7, bn = blockIdx.x << 7;
    const int lr = lane >> 2, lc = lane & 3;
    const int arow = lane & 15, acol8 = (lane >> 4) * 8;
    const int sel = lane >> 3;
    const int brow = (sel & 1) * 8 + (lane & 7), bcol = (sel >> 1) * 8;
    const int NIT = K >> 5;

    const int am = tid >> 1, ac = tid & 1;
    const int br = tid >> 4, bc = tid & 15;
    const __half* gA = A + (size_t)(bm + am) * K;
    const __half* gB = W + (size_t)br * N + bn;

    float acc[4][4][4];
    #pragma unroll
    for (int i = 0; i < 4; i++)
        #pragma unroll
        for (int j = 0; j < 4; j++)
            #pragma unroll
            for (int k = 0; k < 4; k++) acc[i][j][k] = 0.f;

    auto load_stage = [&](int s, int kt) {
        __half* Ah = smh + s * STG_H;
        __half* Bh = Ah + A_ST;
        uint32_t sa = smem_to_u32(Ah + am * APADH + ac * 16);
        const __half* ga = gA + (kt << 5) + ac * 16;
        CP16(sa, ga);
        CP16(sa + 16, ga + 8);
        uint32_t sb = smem_to_u32(Bh + br * BPADH + bc * 8);
        const __half* gb = gB + (size_t)(kt << 5) * N + bc * 8;
        CP16(sb, gb);
        CP16(sb + 16 * BPADH * 2, gb + (size_t)16 * N);
    };

    load_stage(0, 0); CP_COMMIT();
    load_stage(1, 1); CP_COMMIT();
    load_stage(2, 2); CP_COMMIT();

    for (int it = 0; it < NIT; it++) {
        CP_WAIT2();
        __syncthreads();
        if (it + 3 < NIT) load_stage((it + 3) % NSTG, it + 3);
        CP_COMMIT();

        const __half* Ah = smh + (it % NSTG) * STG_H;
        const __half* Bh = Ah + A_ST;
        const uint32_t abase = smem_to_u32(Ah);
        const uint32_t bbase = smem_to_u32(Bh);
        #pragma unroll
        for (int kk = 0; kk < 2; kk++) {
            uint32_t bfr[4][2];
            #pragma unroll
            for (int ntp = 0; ntp < 2; ntp++) {
                uint32_t addr = bbase +
                    ((kk * 16 + brow) * BPADH + wn * 32 + ntp * 16 + bcol) * 2;
                LDSM4T(bfr[ntp * 2][0], bfr[ntp * 2][1],
                       bfr[ntp * 2 + 1][0], bfr[ntp * 2 + 1][1], addr);
            }
            #pragma unroll
            for (int mt = 0; mt < 4; mt++) {
                uint32_t af[4];
                uint32_t aaddr = abase +
                    ((wm * 64 + mt * 16 + arow) * APADH + kk * 16 + acol8) * 2;
                LDSM4(af[0], af[1], af[2], af[3], aaddr);
                #pragma unroll
                for (int nt = 0; nt < 4; nt++)
                    mma1616(acc[mt][nt], af, bfr[nt]);
            }
        }
    }

    // epilogue
    #pragma unroll
    for (int mt = 0; mt < 4; mt++) {
        #pragma unroll
        for (int nt = 0; nt < 4; nt++) {
            int col = bn + wn * 32 + nt * 8 + lc * 2;
            float2 bv = *(const float2*)(bias + col);
            #pragma unroll
            for (int half = 0; half < 2; half++) {
                size_t row = (size_t)(bm + wm * 64 + mt * 16 + lr + half * 8);
                float v0 = acc[mt][nt][half * 2 + 0] + bv.x;
                float v1 = acc[mt][nt][half * 2 + 1] + bv.y;
                if (EPI == EPI_BIAS_RES) {
                    float2 rv = *(const float2*)(R + row * N + col);
                    v0 += rv.x; v1 += rv.y;
                }
                if (EPI == EPI_BIAS_GELU) {
                    v0 = 0.5f * v0 * (1.f + erff(v0 * 0.7071067811865476f));
                    v1 = 0.5f * v1 * (1.f + erff(v1 * 0.7071067811865476f));
                }
                if (OUTH) {
                    *(__half2*)(Ch + row * N + col) = __floats2half2_rn(v0, v1);
                } else {
                    float2 o = {v0, v1};
                    *(float2*)(Cf + row * N + col) = o;
                }
            }
        }
    }
}

// ---------------- all weights fp32 -> fp16, one launch ---------------------------
#define N4_0 (768 * 2304 / 4)
#define N4_1 (768 * 768 / 4)
#define N4_2 (768 * 3072 / 4)
#define N4_3 (3072 * 768 / 4)
#define N4_ALL (N4_0 + N4_1 + N4_2 + N4_3)

__global__ void cvt_all(const float4* __restrict__ w0, const float4* __restrict__ w1,
                        const float4* __restrict__ w2, const float4* __restrict__ w3,
                        __half2* __restrict__ o0, __half2* __restrict__ o1,
                        __half2* __restrict__ o2, __half2* __restrict__ o3) {
    int i = blockIdx.x * 256 + threadIdx.x;
    const float4* src;
    __half2* dst;
    int j = i;
    if (j < N4_0)                       { src = w0; dst = o0; }
    else if ((j -= N4_0) < N4_1)        { src = w1; dst = o1; }
    else if ((j -= N4_1) < N4_2)        { src = w2; dst = o2; }
    else if ((j -= N4_2) < N4_3)        { src = w3; dst = o3; }
    else return;
    float4 v = src[j];
    dst[j * 2]     = __floats2half2_rn(v.x, v.y);
    dst[j * 2 + 1] = __floats2half2_rn(v.z, v.w);
}

// ---------------- block reduction (256 threads) ----------------------------------
__device__ __forceinline__ float block_sum256(float v) {
    __shared__ float sh[8];
    int lane = threadIdx.x & 31, w = threadIdx.x >> 5;
    #pragma unroll
    for (int o = 16; o > 0; o >>= 1) v += __shfl_down_sync(0xffffffffu, v, o);
    if (lane == 0) sh[w] = v;
    __syncthreads();
    float r = 0.f;
    #pragma unroll
    for (int i = 0; i < 8; i++) r += sh[i];
    __syncthreads();
    return r;
}

// ---------------- LayerNorm (fp16 output) ----------------------------------------
__global__ void ln_kernel(const float* __restrict__ x, const float* __restrict__ w,
                          const float* __restrict__ bb, __half* __restrict__ y) {
    int row = blockIdx.x;
    const float* xr = x + (size_t)row * D_;
    int t = threadIdx.x;
    float v0 = xr[t], v1 = xr[t + 256], v2 = xr[t + 512];
    float s = block_sum256(v0 + v1 + v2);
    float mu = s * (1.f / 768.f);
    float d0 = v0 - mu, d1 = v1 - mu, d2 = v2 - mu;
    float vs = block_sum256(d0 * d0 + d1 * d1 + d2 * d2);
    float rstd = rsqrtf(vs * (1.f / 768.f) + 1e-5f);
    __half* yr = y + (size_t)row * D_;
    yr[t]       = __float2half(d0 * rstd * w[t]       + bb[t]);
    yr[t + 256] = __float2half(d1 * rstd * w[t + 256] + bb[t + 256]);
    yr[t + 512] = __float2half(d2 * rstd * w[t + 512] + bb[t + 512]);
}

// ---------------- Attention: fp16 tensor-core flash, windowed causal -------------
#define TQ 128
#define QPH 72
#define KPH 72
#define VPH 72
#define ATTN_SMEM_BYTES ((128 * QPH + 64 * KPH + 64 * VPH) * 2 + 256)

__global__ void __launch_bounds__(256, 2) attn_h_kernel(
    const __half* __restrict__ qkv, const int* __restrict__ amask,
    __half* __restrict__ out)
{
    extern __shared__ char dynsm[];
    __half* Qs = (__half*)dynsm;
    __half* Kn = Qs + 128 * QPH;
    __half* Vs = Kn + 64 * KPH;
    int* kmsk = (int*)(Vs + 64 * VPH);

    const int qi = blockIdx.x, h = blockIdx.y, b = blockIdx.z;
    const int qb = qi * TQ;
    const int tid = threadIdx.x, wid = tid >> 5, lane = tid & 31;
    const int lr = lane >> 2, lc = lane & 3;
    const int wq = wid * 16;
    const int sel = lane >> 3;
    const int vrow = (sel & 1) * 8 + (lane & 7);
    const int vcol = (sel >> 1) * 8;
    const int krow = (lane & 7) + ((lane >> 4) << 3);
    const int kcol = ((lane >> 3) & 1) * 8;

    {
        int r = tid >> 1, cb = (tid & 1) * 32;
        const __half* src = qkv + (size_t)(b * T_ + qb + r) * (3 * D_) + h * 64 + cb;
        #pragma unroll
        for (int c = 0; c < 4; c++)
            *(uint4*)(Qs + r * QPH + cb + c * 8) = *(const uint4*)(src + c * 8);
    }
    __syncthreads();
    const __half2 sc2 = __floats2half2_rn(0.125f, 0.125f);
    uint32_t qa[4][4];
    #pragma unroll
    for (int kk = 0; kk < 4; kk++) {
        const __half* p = Qs + (size_t)(wq + lr) * QPH + kk * 16 + lc * 2;
        qa[kk][0] = h2u(__hmul2(*(const __half2*)p, sc2));
        qa[kk][1] = h2u(__hmul2(*(const __half2*)(p + 8 * QPH), sc2));
        qa[kk][2] = h2u(__hmul2(*(const __half2*)(p + 8), sc2));
        qa[kk][3] = h2u(__hmul2(*(const __half2*)(p + 8 * QPH + 8), sc2));
    }

    float o[8][4];
    #pragma unroll
    for (int j = 0; j < 8; j++)
        #pragma unroll
        for (int k = 0; k < 4; k++) o[j][k] = 0.f;
    float mrow[2] = {-1e30f, -1e30f}, lrow[2] = {0.f, 0.f};

    int lo = qb - (WIN_ - 1);
    const int kt0 = (lo > 0 ? lo : 0) >> 6;
    const int kt1 = (qb + TQ - 1) >> 6;

    for (int kt = kt0; kt <= kt1; kt++) {
        const int kb = kt * 64;
        __syncthreads();
        {
            int r = tid >> 2, cb = (tid & 3) * 16;
            const __half* kp = qkv + (size_t)(b * T_ + kb + r) * (3 * D_) + D_ + h * 64 + cb;
            *(uint4*)(Kn + r * KPH + cb)     = *(const uint4*)kp;
            *(uint4*)(Kn + r * KPH + cb + 8) = *(const uint4*)(kp + 8);
            *(uint4*)(Vs + r * VPH + cb)     = *(const uint4*)(kp + D_);
            *(uint4*)(Vs + r * VPH + cb + 8) = *(const uint4*)(kp + D_ + 8);
            if (tid < 64) kmsk[tid] = amask[b * T_ + kb + tid];
        }
        __syncthreads();

        float s[8][4];
        #pragma unroll
        for (int j = 0; j < 8; j++)
            s[j][0] = s[j][1] = s[j][2] = s[j][3] = 0.f;
        const uint32_t kbase = smem_to_u32(Kn);
        #pragma unroll
        for (int jp = 0; jp < 4; jp++) {
            #pragma unroll
            for (int kk = 0; kk < 4; kk++) {
                uint32_t kb4[4];
                uint32_t addr = kbase + ((jp * 16 + krow) * KPH + kk * 16 + kcol) * 2;
                LDSM4(kb4[0], kb4[1], kb4[2], kb4[3], addr);
                mma1616(s[jp * 2],     qa[kk], kb4);
                mma1616(s[jp * 2 + 1], qa[kk], kb4 + 2);
            }
        }

        #pragma unroll
        for (int j = 0; j < 8; j++) {
            int kg0 = kb + j * 8 + lc * 2, kg1 = kg0 + 1;
            int km0 = kmsk[j * 8 + lc * 2], km1 = kmsk[j * 8 + lc * 2 + 1];
            #pragma unroll
            for (int half = 0; half < 2; half++) {
                int qg = qb + wq + lr + half * 8;
                bool v0 = (kg0 <= qg) && (kg0 > qg - WIN_) && (km0 != 0);
                bool v1 = (kg1 <= qg) && (kg1 > qg - WIN_) && (km1 != 0);
                if (!v0) s[j][half * 2 + 0] = -1e30f;
                if (!v1) s[j][half * 2 + 1] = -1e30f;
            }
        }

        float mnew[2], alpha[2], lsum[2];
        #pragma unroll
        for (int half = 0; half < 2; half++) {
            float m = -1e30f;
            #pragma unroll
            for (int j = 0; j < 8; j++)
                m = fmaxf(m, fmaxf(s[j][half * 2], s[j][half * 2 + 1]));
            m = fmaxf(m, __shfl_xor_sync(0xffffffffu, m, 1));
            m = fmaxf(m, __shfl_xor_sync(0xffffffffu, m, 2));
            mnew[half] = fmaxf(mrow[half], m);
            alpha[half] = __expf(mrow[half] - mnew[half]);
            lsum[half] = 0.f;
        }
        #pragma unroll
        for (int j = 0; j < 8; j++) {
            #pragma unroll
            for (int half = 0; half < 2; half++) {
                float s0 = s[j][half * 2], s1 = s[j][half * 2 + 1];
                float p0 = (s0 <= -1e29f) ? 0.f : __expf(s0 - mnew[half]);
                float p1 = (s1 <= -1e29f) ? 0.f : __expf(s1 - mnew[half]);
                s[j][half * 2] = p0; s[j][half * 2 + 1] = p1;
                lsum[half] += p0 + p1;
            }
        }
        #pragma unroll
        for (int half = 0; half < 2; half++) {
            lsum[half] += __shfl_xor_sync(0xffffffffu, lsum[half], 1);
            lsum[half] += __shfl_xor_sync(0xffffffffu, lsum[half], 2);
            lrow[half] = lrow[half] * alpha[half] + lsum[half];
            mrow[half] = mnew[half];
        }
        #pragma unroll
        for (int j = 0; j < 8; j++) {
            o[j][0] *= alpha[0]; o[j][1] *= alpha[0];
            o[j][2] *= alpha[1]; o[j][3] *= alpha[1];
        }

        const uint32_t vbase = smem_to_u32(Vs);
        #pragma unroll
        for (int kk = 0; kk < 4; kk++) {
            uint32_t pa[4] = {
                h2u(__floats2half2_rn(s[2 * kk][0],     s[2 * kk][1])),
                h2u(__floats2half2_rn(s[2 * kk][2],     s[2 * kk][3])),
                h2u(__floats2half2_rn(s[2 * kk + 1][0], s[2 * kk + 1][1])),
                h2u(__floats2half2_rn(s[2 * kk + 1][2], s[2 * kk + 1][3]))
            };
            #pragma unroll
            for (int jp = 0; jp < 4; jp++) {
                uint32_t vb[4];
                uint32_t addr = vbase + ((kk * 16 + vrow) * VPH + jp * 16 + vcol) * 2;
                LDSM4T(vb[0], vb[1], vb[2], vb[3], addr);
                mma1616(o[jp * 2],     pa, vb);
                mma1616(o[jp * 2 + 1], pa, vb + 2);
            }
        }
    }

    float linv[2] = {1.f / lrow[0], 1.f / lrow[1]};
    #pragma unroll
    for (int half = 0; half < 2; half++) {
        size_t row = (size_t)(b * T_ + qb + wq + lr + half * 8);
        __half* op = out + row * D_ + h * 64;
        #pragma unroll
        for (int j = 0; j < 8; j++)
            *(__half2*)(op + j * 8 + lc * 2) =
                __floats2half2_rn(o[j][half * 2] * linv[half], o[j][half * 2 + 1] * linv[half]);
    }
}

// ---------------- launch -----------------------------------------------------------
extern "C" void kernel_launch(void* const* d_in, const int* in_sizes, int n_in,
                              void* d_out, int out_size)
{
    const float* x      = (const float*)d_in[0];
    const int*   amask  = (const int*)d_in[1];
    const float* ln1_w  = (const float*)d_in[2];
    const float* ln1_b  = (const float*)d_in[3];
    const float* w_attn = (const float*)d_in[4];
    const float* b_attn = (const float*)d_in[5];
    const float* w_proj = (const float*)d_in[6];
    const float* b_proj = (const float*)d_in[7];
    const float* ln2_w  = (const float*)d_in[8];
    const float* ln2_b  = (const float*)d_in[9];
    const float* w_fc   = (const float*)d_in[10];
    const float* b_fc   = (const float*)d_in[11];
    const float* w_fcp  = (const float*)d_in[12];
    const float* b_fcp  = (const float*)d_in[13];
    float* out = (float*)d_out;

    __half *p_x1h, *p_qkvh, *p_attnh, *p_hh, *p_wah, *p_wph, *p_wfh, *p_wfph;
    float* p_x2;
    cudaGetSymbolAddress((void**)&p_x1h,   g_x1h);
    cudaGetSymbolAddress((void**)&p_qkvh,  g_qkvh);
    cudaGetSymbolAddress((void**)&p_attnh, g_attnh);
    cudaGetSymbolAddress((void**)&p_x2,    g_x2);
    cudaGetSymbolAddress((void**)&p_hh,    g_hh);
    cudaGetSymbolAddress((void**)&p_wah,   g_wah);
    cudaGetSymbolAddress((void**)&p_wph,   g_wph);
    cudaGetSymbolAddress((void**)&p_wfh,   g_wfh);
    cudaGetSymbolAddress((void**)&p_wfph,  g_wfph);

    cudaFuncSetAttribute(hgemm<EPI_BIAS, true>,       cudaFuncAttributeMaxDynamicSharedMemorySize, GEMM_SMEM);
    cudaFuncSetAttribute(hgemm<EPI_BIAS_RES, false>,  cudaFuncAttributeMaxDynamicSharedMemorySize, GEMM_SMEM);
    cudaFuncSetAttribute(hgemm<EPI_BIAS_GELU, true>,  cudaFuncAttributeMaxDynamicSharedMemorySize, GEMM_SMEM);
    cudaFuncSetAttribute(attn_h_kernel, cudaFuncAttributeMaxDynamicSharedMemorySize, ATTN_SMEM_BYTES);

    // all weights fp32 -> fp16, single launch
    cvt_all<<<(N4_ALL + 255) / 256, 256>>>(
        (const float4*)w_attn, (const float4*)w_proj, (const float4*)w_fc, (const float4*)w_fcp,
        (__half2*)p_wah, (__half2*)p_wph, (__half2*)p_wfh, (__half2*)p_wfph);

    // 1) ln1 -> fp16
    ln_kernel<<<M_, 256>>>(x, ln1_w, ln1_b, p_x1h);
    // 2) qkv = x1 @ w_attn + b_attn   [8192 x 2304 x 768], fp16 out
    hgemm<EPI_BIAS, true><<<dim3(2304 / 128, M_ / 128), 256, GEMM_SMEM>>>(
        p_x1h, p_wah, b_attn, nullptr, nullptr, p_qkvh, 2304, 768);
    // 3) attention (fp16 tensor-core flash)
    attn_h_kernel<<<dim3(T_ / TQ, H_, B_), 256, ATTN_SMEM_BYTES>>>(p_qkvh, amask, p_attnh);
    // 4) x2 = attn @ w_proj + b_proj + x   [8192 x 768 x 768], fp32 out
    hgemm<EPI_BIAS_RES, false><<<dim3(768 / 128, M_ / 128), 256, GEMM_SMEM>>>(
        p_attnh, p_wph, b_proj, x, p_x2, nullptr, 768, 768);
    // 5) ln2 -> fp16
    ln_kernel<<<M_, 256>>>(p_x2, ln2_w, ln2_b, p_x1h);
    // 6) h = gelu(x1 @ w_fc + b_fc)   [8192 x 3072 x 768], fp16 out
    hgemm<EPI_BIAS_GELU, true><<<dim3(3072 / 128, M_ / 128), 256, GEMM_SMEM>>>(
        p_x1h, p_wfh, b_fc, nullptr, nullptr, p_hh, 3072, 768);
    // 7) out = h @ w_fc_proj + b_fc_proj + x2   [8192 x 768 x 3072], fp32 out
    hgemm<EPI_BIAS_RES, false><<<dim3(768 / 128, M_ / 128), 256, GEMM_SMEM>>>(
        p_hh, p_wfph, b_fcp, p_x2, out, nullptr, 768, 3072);
}

// round 8
// speedup vs baseline: 1.0439x; 1.0439x over previous
#include <cuda_runtime.h>
#include <cuda_fp16.h>
#include <math.h>
#include <stdint.h>

#define B_   8
#define T_   1024
#define D_   768
#define H_   12
#define WIN_ 768
#define M_   (B_*T_)   // 8192

// ---------------- scratch (static device globals) ---------------------------
__device__ __half g_x1h[M_ * D_];
__device__ __half g_qkvh[M_ * 3 * D_];
__device__ __half g_attnh[M_ * D_];
__device__ float  g_x2[M_ * D_];
__device__ __half g_hh[M_ * 4 * D_];
__device__ __half g_wah[D_ * 3 * D_];
__device__ __half g_wph[D_ * D_];
__device__ __half g_wfh[D_ * 4 * D_];
__device__ __half g_wfph[4 * D_ * D_];

// ---------------- helpers -----------------------------------------------------
__device__ __forceinline__ uint32_t smem_to_u32(const void* p) {
    uint32_t a;
    asm("{ .reg .u64 t; cvta.to.shared.u64 t, %1; cvt.u32.u64 %0, t; }" : "=r"(a) : "l"(p));
    return a;
}
__device__ __forceinline__ uint32_t h2u(__half2 v) { return *(uint32_t*)&v; }

#define CP16(saddr, gptr) \
    asm volatile("cp.async.cg.shared.global [%0], [%1], 16;" :: "r"(saddr), "l"(gptr))
#define CP_COMMIT() asm volatile("cp.async.commit_group;" ::: "memory")
#define CP_WAIT2()  asm volatile("cp.async.wait_group 2;" ::: "memory")

#define LDSM4(r0, r1, r2, r3, addr) \
    asm volatile("ldmatrix.sync.aligned.m8n8.x4.shared.b16 {%0,%1,%2,%3}, [%4];" \
        : "=r"(r0), "=r"(r1), "=r"(r2), "=r"(r3) : "r"(addr))
#define LDSM4T(r0, r1, r2, r3, addr) \
    asm volatile("ldmatrix.sync.aligned.m8n8.x4.trans.shared.b16 {%0,%1,%2,%3}, [%4];" \
        : "=r"(r0), "=r"(r1), "=r"(r2), "=r"(r3) : "r"(addr))

__device__ __forceinline__ void mma1616(float* d, const uint32_t* a, const uint32_t* b) {
    asm volatile(
        "mma.sync.aligned.m16n8k16.row.col.f32.f16.f16.f32 "
        "{%0,%1,%2,%3}, {%4,%5,%6,%7}, {%8,%9}, {%0,%1,%2,%3};"
        : "+f"(d[0]), "+f"(d[1]), "+f"(d[2]), "+f"(d[3])
        : "r"(a[0]), "r"(a[1]), "r"(a[2]), "r"(a[3]), "r"(b[0]), "r"(b[1]));
}

// ---------------- fp16 tensor-core GEMM ----------------------------------------
enum { EPI_BIAS = 0, EPI_BIAS_RES = 1, EPI_BIAS_GELU = 2 };

#define NSTG 4
#define APADH 40
#define BPADH 136
#define A_ST (128 * APADH)
#define B_ST (32 * BPADH)
#define STG_H (A_ST + B_ST)
#define GEMM_SMEM (NSTG * STG_H * 2)

template <int EPI, bool OUTH>
__global__ void __launch_bounds__(256, 2) hgemm(
    const __half* __restrict__ A, const __half* __restrict__ W,
    const float* __restrict__ bias, const float* __restrict__ R,
    float* __restrict__ Cf, __half* __restrict__ Ch, int N, int K)
{
    extern __shared__ char dynsm[];
    __half* smh = (__half*)dynsm;
    const int tid = threadIdx.x;
    const int wid = tid >> 5, lane = tid & 31;
    const int wm = wid >> 2, wn = wid & 3;
    const int bm = blockIdx.y << 7, bn = blockIdx.x << 7;
    const int lr = lane >> 2, lc = lane & 3;
    const int arow = lane & 15, acol8 = (lane >> 4) * 8;
    const int sel = lane >> 3;
    const int brow = (sel & 1) * 8 + (lane & 7), bcol = (sel >> 1) * 8;
    const int NIT = K >> 5;

    const int am = tid >> 1, ac = tid & 1;
    const int br = tid >> 4, bc = tid & 15;
    const __half* gA = A + (size_t)(bm + am) * K;
    const __half* gB = W + (size_t)br * N + bn;

    float acc[4][4][4];
    #pragma unroll
    for (int i = 0; i < 4; i++)
        #pragma unroll
        for (int j = 0; j < 4; j++)
            #pragma unroll
            for (int k = 0; k < 4; k++) acc[i][j][k] = 0.f;

    auto load_stage = [&](int s, int kt) {
        __half* Ah = smh + s * STG_H;
        __half* Bh = Ah + A_ST;
        uint32_t sa = smem_to_u32(Ah + am * APADH + ac * 16);
        const __half* ga = gA + (kt << 5) + ac * 16;
        CP16(sa, ga);
        CP16(sa + 16, ga + 8);
        uint32_t sb = smem_to_u32(Bh + br * BPADH + bc * 8);
        const __half* gb = gB + (size_t)(kt << 5) * N + bc * 8;
        CP16(sb, gb);
        CP16(sb + 16 * BPADH * 2, gb + (size_t)16 * N);
    };

    load_stage(0, 0); CP_COMMIT();
    load_stage(1, 1); CP_COMMIT();
    load_stage(2, 2); CP_COMMIT();

    for (int it = 0; it < NIT; it++) {
        CP_WAIT2();
        __syncthreads();
        if (it + 3 < NIT) load_stage((it + 3) % NSTG, it + 3);
        CP_COMMIT();

        const __half* Ah = smh + (it % NSTG) * STG_H;
        const __half* Bh = Ah + A_ST;
        const uint32_t abase = smem_to_u32(Ah);
        const uint32_t bbase = smem_to_u32(Bh);
        #pragma unroll
        for (int kk = 0; kk < 2; kk++) {
            uint32_t bfr[4][2];
            #pragma unroll
            for (int ntp = 0; ntp < 2; ntp++) {
                uint32_t addr = bbase +
                    ((kk * 16 + brow) * BPADH + wn * 32 + ntp * 16 + bcol) * 2;
                LDSM4T(bfr[ntp * 2][0], bfr[ntp * 2][1],
                       bfr[ntp * 2 + 1][0], bfr[ntp * 2 + 1][1], addr);
            }
            #pragma unroll
            for (int mt = 0; mt < 4; mt++) {
                uint32_t af[4];
                uint32_t aaddr = abase +
                    ((wm * 64 + mt * 16 + arow) * APADH + kk * 16 + acol8) * 2;
                LDSM4(af[0], af[1], af[2], af[3], aaddr);
                #pragma unroll
                for (int nt = 0; nt < 4; nt++)
                    mma1616(acc[mt][nt], af, bfr[nt]);
            }
        }
    }

    #pragma unroll
    for (int mt = 0; mt < 4; mt++) {
        #pragma unroll
        for (int nt = 0; nt < 4; nt++) {
            int col = bn + wn * 32 + nt * 8 + lc * 2;
            float2 bv = *(const float2*)(bias + col);
            #pragma unroll
            for (int half = 0; half < 2; half++) {
                size_t row = (size_t)(bm + wm * 64 + mt * 16 + lr + half * 8);
                float v0 = acc[mt][nt][half * 2 + 0] + bv.x;
                float v1 = acc[mt][nt][half * 2 + 1] + bv.y;
                if (EPI == EPI_BIAS_RES) {
                    float2 rv = *(const float2*)(R + row * N + col);
                    v0 += rv.x; v1 += rv.y;
                }
                if (EPI == EPI_BIAS_GELU) {
                    v0 = 0.5f * v0 * (1.f + erff(v0 * 0.7071067811865476f));
                    v1 = 0.5f * v1 * (1.f + erff(v1 * 0.7071067811865476f));
                }
                if (OUTH) {
                    *(__half2*)(Ch + row * N + col) = __floats2half2_rn(v0, v1);
                } else {
                    float2 o = {v0, v1};
                    *(float2*)(Cf + row * N + col) = o;
                }
            }
        }
    }
}

// ---------------- all weights fp32 -> fp16, one launch ---------------------------
#define N4_0 (768 * 2304 / 4)
#define N4_1 (768 * 768 / 4)
#define N4_2 (768 * 3072 / 4)
#define N4_3 (3072 * 768 / 4)
#define N4_ALL (N4_0 + N4_1 + N4_2 + N4_3)

__global__ void cvt_all(const float4* __restrict__ w0, const float4* __restrict__ w1,
                        const float4* __restrict__ w2, const float4* __restrict__ w3,
                        __half2* __restrict__ o0, __half2* __restrict__ o1,
                        __half2* __restrict__ o2, __half2* __restrict__ o3) {
    int i = blockIdx.x * 256 + threadIdx.x;
    const float4* src;
    __half2* dst;
    int j = i;
    if (j < N4_0)                { src = w0; dst = o0; }
    else if ((j -= N4_0) < N4_1) { src = w1; dst = o1; }
    else if ((j -= N4_1) < N4_2) { src = w2; dst = o2; }
    else if ((j -= N4_2) < N4_3) { src = w3; dst = o3; }
    else return;
    float4 v = src[j];
    dst[j * 2]     = __floats2half2_rn(v.x, v.y);
    dst[j * 2 + 1] = __floats2half2_rn(v.z, v.w);
}

// ---------------- LayerNorm: warp per row, shfl-only reductions -------------------
__global__ void __launch_bounds__(256) ln_kernel(
    const float* __restrict__ x, const float* __restrict__ w,
    const float* __restrict__ bb, __half* __restrict__ y)
{
    const int warp = threadIdx.x >> 5, lane = threadIdx.x & 31;
    const size_t row = (size_t)blockIdx.x * 8 + warp;
    const float* xr = x + row * D_;

    float4 v[6];
    float s = 0.f;
    #pragma unroll
    for (int i = 0; i < 6; i++) {
        v[i] = *(const float4*)(xr + (i * 32 + lane) * 4);
        s += v[i].x + v[i].y + v[i].z + v[i].w;
    }
    #pragma unroll
    for (int o = 16; o > 0; o >>= 1) s += __shfl_xor_sync(0xffffffffu, s, o);
    const float mu = s * (1.f / 768.f);

    float vs = 0.f;
    #pragma unroll
    for (int i = 0; i < 6; i++) {
        v[i].x -= mu; v[i].y -= mu; v[i].z -= mu; v[i].w -= mu;
        vs += v[i].x * v[i].x + v[i].y * v[i].y + v[i].z * v[i].z + v[i].w * v[i].w;
    }
    #pragma unroll
    for (int o = 16; o > 0; o >>= 1) vs += __shfl_xor_sync(0xffffffffu, vs, o);
    const float rstd = rsqrtf(vs * (1.f / 768.f) + 1e-5f);

    __half* yr = y + row * D_;
    #pragma unroll
    for (int i = 0; i < 6; i++) {
        int c = (i * 32 + lane) * 4;
        float4 wv = *(const float4*)(w + c);
        float4 bv = *(const float4*)(bb + c);
        __half2 h0 = __floats2half2_rn(v[i].x * rstd * wv.x + bv.x,
                                       v[i].y * rstd * wv.y + bv.y);
        __half2 h1 = __floats2half2_rn(v[i].z * rstd * wv.z + bv.z,
                                       v[i].w * rstd * wv.w + bv.w);
        uint2 pack = {h2u(h0), h2u(h1)};
        *(uint2*)(yr + c) = pack;
    }
}

// ---------------- Attention: fp16 tensor-core flash, windowed causal -------------
// Interior-tile fast path: tiles fully inside causal+window+mask skip all
// predicate work and the guarded-exp path.
#define TQ 128
#define QPH 72
#define KPH 72
#define VPH 72
#define ATTN_SMEM_BYTES ((128 * QPH + 64 * KPH + 64 * VPH) * 2 + 256 + 16)

__global__ void __launch_bounds__(256, 2) attn_h_kernel(
    const __half* __restrict__ qkv, const int* __restrict__ amask,
    __half* __restrict__ out)
{
    extern __shared__ char dynsm[];
    __half* Qs = (__half*)dynsm;
    __half* Kn = Qs + 128 * QPH;
    __half* Vs = Kn + 64 * KPH;
    int* kmsk = (int*)(Vs + 64 * VPH);
    int* mflag = kmsk + 64;   // [2] per-warp allmask flags

    const int qi = blockIdx.x, h = blockIdx.y, b = blockIdx.z;
    const int qb = qi * TQ;
    const int tid = threadIdx.x, wid = tid >> 5, lane = tid & 31;
    const int lr = lane >> 2, lc = lane & 3;
    const int wq = wid * 16;
    const int sel = lane >> 3;
    const int vrow = (sel & 1) * 8 + (lane & 7);
    const int vcol = (sel >> 1) * 8;
    const int krow = (lane & 7) + ((lane >> 4) << 3);
    const int kcol = ((lane >> 3) & 1) * 8;

    {
        int r = tid >> 1, cb = (tid & 1) * 32;
        const __half* src = qkv + (size_t)(b * T_ + qb + r) * (3 * D_) + h * 64 + cb;
        #pragma unroll
        for (int c = 0; c < 4; c++)
            *(uint4*)(Qs + r * QPH + cb + c * 8) = *(const uint4*)(src + c * 8);
    }
    __syncthreads();
    const __half2 sc2 = __floats2half2_rn(0.125f, 0.125f);
    uint32_t qa[4][4];
    #pragma unroll
    for (int kk = 0; kk < 4; kk++) {
        const __half* p = Qs + (size_t)(wq + lr) * QPH + kk * 16 + lc * 2;
        qa[kk][0] = h2u(__hmul2(*(const __half2*)p, sc2));
        qa[kk][1] = h2u(__hmul2(*(const __half2*)(p + 8 * QPH), sc2));
        qa[kk][2] = h2u(__hmul2(*(const __half2*)(p + 8), sc2));
        qa[kk][3] = h2u(__hmul2(*(const __half2*)(p + 8 * QPH + 8), sc2));
    }

    float o[8][4];
    #pragma unroll
    for (int j = 0; j < 8; j++)
        #pragma unroll
        for (int k = 0; k < 4; k++) o[j][k] = 0.f;
    float mrow[2] = {-1e30f, -1e30f}, lrow[2] = {0.f, 0.f};

    int lo = qb - (WIN_ - 1);
    const int kt0 = (lo > 0 ? lo : 0) >> 6;
    const int kt1 = (qb + TQ - 1) >> 6;

    for (int kt = kt0; kt <= kt1; kt++) {
        const int kb = kt * 64;
        __syncthreads();
        {
            int r = tid >> 2, cb = (tid & 3) * 16;
            const __half* kp = qkv + (size_t)(b * T_ + kb + r) * (3 * D_) + D_ + h * 64 + cb;
            *(uint4*)(Kn + r * KPH + cb)     = *(const uint4*)kp;
            *(uint4*)(Kn + r * KPH + cb + 8) = *(const uint4*)(kp + 8);
            *(uint4*)(Vs + r * VPH + cb)     = *(const uint4*)(kp + D_);
            *(uint4*)(Vs + r * VPH + cb + 8) = *(const uint4*)(kp + D_ + 8);
            if (tid < 64) {
                int mv = amask[b * T_ + kb + tid];
                kmsk[tid] = mv;
                unsigned bal = __ballot_sync(0xffffffffu, mv != 0);
                if ((tid & 31) == 0) mflag[tid >> 5] = (bal == 0xffffffffu);
            }
        }
        __syncthreads();

        const bool tilefull = (kb + 63 <= qb) && (kb >= qb - 640) &&
                              mflag[0] && mflag[1];

        float s[8][4];
        #pragma unroll
        for (int j = 0; j < 8; j++)
            s[j][0] = s[j][1] = s[j][2] = s[j][3] = 0.f;
        const uint32_t kbase = smem_to_u32(Kn);
        #pragma unroll
        for (int jp = 0; jp < 4; jp++) {
            #pragma unroll
            for (int kk = 0; kk < 4; kk++) {
                uint32_t kb4[4];
                uint32_t addr = kbase + ((jp * 16 + krow) * KPH + kk * 16 + kcol) * 2;
                LDSM4(kb4[0], kb4[1], kb4[2], kb4[3], addr);
                mma1616(s[jp * 2],     qa[kk], kb4);
                mma1616(s[jp * 2 + 1], qa[kk], kb4 + 2);
            }
        }

        if (!tilefull) {
            #pragma unroll
            for (int j = 0; j < 8; j++) {
                int kg0 = kb + j * 8 + lc * 2, kg1 = kg0 + 1;
                int km0 = kmsk[j * 8 + lc * 2], km1 = kmsk[j * 8 + lc * 2 + 1];
                #pragma unroll
                for (int half = 0; half < 2; half++) {
                    int qg = qb + wq + lr + half * 8;
                    bool v0 = (kg0 <= qg) && (kg0 > qg - WIN_) && (km0 != 0);
                    bool v1 = (kg1 <= qg) && (kg1 > qg - WIN_) && (km1 != 0);
                    if (!v0) s[j][half * 2 + 0] = -1e30f;
                    if (!v1) s[j][half * 2 + 1] = -1e30f;
                }
            }
        }

        float mnew[2], alpha[2], lsum[2];
        #pragma unroll
        for (int half = 0; half < 2; half++) {
            float m = -1e30f;
            #pragma unroll
            for (int j = 0; j < 8; j++)
                m = fmaxf(m, fmaxf(s[j][half * 2], s[j][half * 2 + 1]));
            m = fmaxf(m, __shfl_xor_sync(0xffffffffu, m, 1));
            m = fmaxf(m, __shfl_xor_sync(0xffffffffu, m, 2));
            mnew[half] = fmaxf(mrow[half], m);
            alpha[half] = __expf(mrow[half] - mnew[half]);
            lsum[half] = 0.f;
        }
        if (tilefull) {
            #pragma unroll
            for (int j = 0; j < 8; j++) {
                #pragma unroll
                for (int half = 0; half < 2; half++) {
                    float p0 = __expf(s[j][half * 2]     - mnew[half]);
                    float p1 = __expf(s[j][half * 2 + 1] - mnew[half]);
                    s[j][half * 2] = p0; s[j][half * 2 + 1] = p1;
                    lsum[half] += p0 + p1;
                }
            }
        } else {
            #pragma unroll
            for (int j = 0; j < 8; j++) {
                #pragma unroll
                for (int half = 0; half < 2; half++) {
                    float s0 = s[j][half * 2], s1 = s[j][half * 2 + 1];
                    float p0 = (s0 <= -1e29f) ? 0.f : __expf(s0 - mnew[half]);
                    float p1 = (s1 <= -1e29f) ? 0.f : __expf(s1 - mnew[half]);
                    s[j][half * 2] = p0; s[j][half * 2 + 1] = p1;
                    lsum[half] += p0 + p1;
                }
            }
        }
        #pragma unroll
        for (int half = 0; half < 2; half++) {
            lsum[half] += __shfl_xor_sync(0xffffffffu, lsum[half], 1);
            lsum[half] += __shfl_xor_sync(0xffffffffu, lsum[half], 2);
            lrow[half] = lrow[half] * alpha[half] + lsum[half];
            mrow[half] = mnew[half];
        }
        #pragma unroll
        for (int j = 0; j < 8; j++) {
            o[j][0] *= alpha[0]; o[j][1] *= alpha[0];
            o[j][2] *= alpha[1]; o[j][3] *= alpha[1];
        }

        const uint32_t vbase = smem_to_u32(Vs);
        #pragma unroll
        for (int kk = 0; kk < 4; kk++) {
            uint32_t pa[4] = {
                h2u(__floats2half2_rn(s[2 * kk][0],     s[2 * kk][1])),
                h2u(__floats2half2_rn(s[2 * kk][2],     s[2 * kk][3])),
                h2u(__floats2half2_rn(s[2 * kk + 1][0], s[2 * kk + 1][1])),
                h2u(__floats2half2_rn(s[2 * kk + 1][2], s[2 * kk + 1][3]))
            };
            #pragma unroll
            for (int jp = 0; jp < 4; jp++) {
                uint32_t vb[4];
                uint32_t addr = vbase + ((kk * 16 + vrow) * VPH + jp * 16 + vcol) * 2;
                LDSM4T(vb[0], vb[1], vb[2], vb[3], addr);
                mma1616(o[jp * 2],     pa, vb);
                mma1616(o[jp * 2 + 1], pa, vb + 2);
            }
        }
    }

    float linv[2] = {1.f / lrow[0], 1.f / lrow[1]};
    #pragma unroll
    for (int half = 0; half < 2; half++) {
        size_t row = (size_t)(b * T_ + qb + wq + lr + half * 8);
        __half* op = out + row * D_ + h * 64;
        #pragma unroll
        for (int j = 0; j < 8; j++)
            *(__half2*)(op + j * 8 + lc * 2) =
                __floats2half2_rn(o[j][half * 2] * linv[half], o[j][half * 2 + 1] * linv[half]);
    }
}

// ---------------- launch -----------------------------------------------------------
extern "C" void kernel_launch(void* const* d_in, const int* in_sizes, int n_in,
                              void* d_out, int out_size)
{
    const float* x      = (const float*)d_in[0];
    const int*   amask  = (const int*)d_in[1];
    const float* ln1_w  = (const float*)d_in[2];
    const float* ln1_b  = (const float*)d_in[3];
    const float* w_attn = (const float*)d_in[4];
    const float* b_attn = (const float*)d_in[5];
    const float* w_proj = (const float*)d_in[6];
    const float* b_proj = (const float*)d_in[7];
    const float* ln2_w  = (const float*)d_in[8];
    const float* ln2_b  = (const float*)d_in[9];
    const float* w_fc   = (const float*)d_in[10];
    const float* b_fc   = (const float*)d_in[11];
    const float* w_fcp  = (const float*)d_in[12];
    const float* b_fcp  = (const float*)d_in[13];
    float* out = (float*)d_out;

    __half *p_x1h, *p_qkvh, *p_attnh, *p_hh, *p_wah, *p_wph, *p_wfh, *p_wfph;
    float* p_x2;
    cudaGetSymbolAddress((void**)&p_x1h,   g_x1h);
    cudaGetSymbolAddress((void**)&p_qkvh,  g_qkvh);
    cudaGetSymbolAddress((void**)&p_attnh, g_attnh);
    cudaGetSymbolAddress((void**)&p_x2,    g_x2);
    cudaGetSymbolAddress((void**)&p_hh,    g_hh);
    cudaGetSymbolAddress((void**)&p_wah,   g_wah);
    cudaGetSymbolAddress((void**)&p_wph,   g_wph);
    cudaGetSymbolAddress((void**)&p_wfh,   g_wfh);
    cudaGetSymbolAddress((void**)&p_wfph,  g_wfph);

    cudaFuncSetAttribute(hgemm<EPI_BIAS, true>,       cudaFuncAttributeMaxDynamicSharedMemorySize, GEMM_SMEM);
    cudaFuncSetAttribute(hgemm<EPI_BIAS_RES, false>,  cudaFuncAttributeMaxDynamicSharedMemorySize, GEMM_SMEM);
    cudaFuncSetAttribute(hgemm<EPI_BIAS_GELU, true>,  cudaFuncAttributeMaxDynamicSharedMemorySize, GEMM_SMEM);
    cudaFuncSetAttribute(attn_h_kernel, cudaFuncAttributeMaxDynamicSharedMemorySize, ATTN_SMEM_BYTES);

    cvt_all<<<(N4_ALL + 255) / 256, 256>>>(
        (const float4*)w_attn, (const float4*)w_proj, (const float4*)w_fc, (const float4*)w_fcp,
        (__half2*)p_wah, (__half2*)p_wph, (__half2*)p_wfh, (__half2*)p_wfph);

    // 1) ln1 -> fp16
    ln_kernel<<<M_ / 8, 256>>>(x, ln1_w, ln1_b, p_x1h);
    // 2) qkv = x1 @ w_attn + b_attn
    hgemm<EPI_BIAS, true><<<dim3(2304 / 128, M_ / 128), 256, GEMM_SMEM>>>(
        p_x1h, p_wah, b_attn, nullptr, nullptr, p_qkvh, 2304, 768);
    // 3) attention
    attn_h_kernel<<<dim3(T_ / TQ, H_, B_), 256, ATTN_SMEM_BYTES>>>(p_qkvh, amask, p_attnh);
    // 4) x2 = attn @ w_proj + b_proj + x
    hgemm<EPI_BIAS_RES, false><<<dim3(768 / 128, M_ / 128), 256, GEMM_SMEM>>>(
        p_attnh, p_wph, b_proj, x, p_x2, nullptr, 768, 768);
    // 5) ln2 -> fp16
    ln_kernel<<<M_ / 8, 256>>>(p_x2, ln2_w, ln2_b, p_x1h);
    // 6) h = gelu(x1 @ w_fc + b_fc)
    hgemm<EPI_BIAS_GELU, true><<<dim3(3072 / 128, M_ / 128), 256, GEMM_SMEM>>>(
        p_x1h, p_wfh, b_fc, nullptr, nullptr, p_hh, 3072, 768);
    // 7) out = h @ w_fc_proj + b_fc_proj + x2
    hgemm<EPI_BIAS_RES, false><<<dim3(768 / 128, M_ / 128), 256, GEMM_SMEM>>>(
        p_hh, p_wfph, b_fcp, p_x2, out, nullptr, 768, 3072);
}

// round 9
// speedup vs baseline: 1.0442x; 1.0002x over previous
#include <cuda_runtime.h>
#include <cuda_fp16.h>
#include <math.h>
#include <stdint.h>

#define B_   8
#define T_   1024
#define D_   768
#define H_   12
#define WIN_ 768
#define M_   (B_*T_)   // 8192

// ---------------- scratch (static device globals) ---------------------------
__device__ __half g_x1h[M_ * D_];
__device__ __half g_qkvh[M_ * 3 * D_];
__device__ __half g_attnh[M_ * D_];
__device__ float  g_x2[M_ * D_];
__device__ __half g_hh[M_ * 4 * D_];
__device__ __half g_wah[D_ * 3 * D_];
__device__ __half g_wph[D_ * D_];
__device__ __half g_wfh[D_ * 4 * D_];
__device__ __half g_wfph[4 * D_ * D_];

// ---------------- helpers -----------------------------------------------------
__device__ __forceinline__ uint32_t smem_to_u32(const void* p) {
    uint32_t a;
    asm("{ .reg .u64 t; cvta.to.shared.u64 t, %1; cvt.u32.u64 %0, t; }" : "=r"(a) : "l"(p));
    return a;
}
__device__ __forceinline__ uint32_t h2u(__half2 v) { return *(uint32_t*)&v; }

#define CP16(saddr, gptr) \
    asm volatile("cp.async.cg.shared.global [%0], [%1], 16;" :: "r"(saddr), "l"(gptr))
#define CP_COMMIT() asm volatile("cp.async.commit_group;" ::: "memory")
#define CP_WAIT2()  asm volatile("cp.async.wait_group 2;" ::: "memory")

#define LDSM4(r0, r1, r2, r3, addr) \
    asm volatile("ldmatrix.sync.aligned.m8n8.x4.shared.b16 {%0,%1,%2,%3}, [%4];" \
        : "=r"(r0), "=r"(r1), "=r"(r2), "=r"(r3) : "r"(addr))
#define LDSM4T(r0, r1, r2, r3, addr) \
    asm volatile("ldmatrix.sync.aligned.m8n8.x4.trans.shared.b16 {%0,%1,%2,%3}, [%4];" \
        : "=r"(r0), "=r"(r1), "=r"(r2), "=r"(r3) : "r"(addr))

__device__ __forceinline__ void mma1616(float* d, const uint32_t* a, const uint32_t* b) {
    asm volatile(
        "mma.sync.aligned.m16n8k16.row.col.f32.f16.f16.f32 "
        "{%0,%1,%2,%3}, {%4,%5,%6,%7}, {%8,%9}, {%0,%1,%2,%3};"
        : "+f"(d[0]), "+f"(d[1]), "+f"(d[2]), "+f"(d[3])
        : "r"(a[0]), "r"(a[1]), "r"(a[2]), "r"(a[3]), "r"(b[0]), "r"(b[1]));
}

// ---------------- fp16 tensor-core GEMM ----------------------------------------
// C[M,N] = A[M,K] @ W[K,N] + bias (+res / gelu). MT x 128 tile (MT=128 or 64),
// BK=32, 8 warps, 4-stage cp.async pipeline, single sync/iter, ldmatrix frags.
enum { EPI_BIAS = 0, EPI_BIAS_RES = 1, EPI_BIAS_GELU = 2 };

#define NSTG 4
#define APADH 40
#define BPADH 136
#define B_ST (32 * BPADH)
#define STG_H_MT(MT) ((MT) * APADH + B_ST)
#define GEMM_SMEM_MT(MT) (NSTG * STG_H_MT(MT) * 2)

template <int EPI, bool OUTH, int MT>
__global__ void __launch_bounds__(256, 2) hgemm(
    const __half* __restrict__ A, const __half* __restrict__ W,
    const float* __restrict__ bias, const float* __restrict__ R,
    float* __restrict__ Cf, __half* __restrict__ Ch, int N, int K)
{
    constexpr int MTW = MT / 32;          // m16 tiles per warp
    constexpr int A_ST = MT * APADH;
    constexpr int STG_H = A_ST + B_ST;

    extern __shared__ char dynsm[];
    __half* smh = (__half*)dynsm;
    const int tid = threadIdx.x;
    const int wid = tid >> 5, lane = tid & 31;
    const int wm = wid >> 2, wn = wid & 3;
    const int bm = blockIdx.y * MT, bn = blockIdx.x << 7;
    const int lr = lane >> 2, lc = lane & 3;
    const int arow = lane & 15, acol8 = (lane >> 4) * 8;
    const int sel = lane >> 3;
    const int brow = (sel & 1) * 8 + (lane & 7), bcol = (sel >> 1) * 8;
    const int NIT = K >> 5;

    // A load coordinates
    const int am = (MT == 128) ? (tid >> 1) : (tid >> 2);
    const int ac = (MT == 128) ? (tid & 1) : (tid & 3);
    const int br = tid >> 4, bc = tid & 15;
    const __half* gA = A + (size_t)(bm + am) * K;
    const __half* gB = W + (size_t)br * N + bn;

    float acc[MTW][4][4];
    #pragma unroll
    for (int i = 0; i < MTW; i++)
        #pragma unroll
        for (int j = 0; j < 4; j++)
            #pragma unroll
            for (int k = 0; k < 4; k++) acc[i][j][k] = 0.f;

    auto load_stage = [&](int s, int kt) {
        __half* Ah = smh + s * STG_H;
        __half* Bh = Ah + A_ST;
        if (MT == 128) {
            uint32_t sa = smem_to_u32(Ah + am * APADH + ac * 16);
            const __half* ga = gA + (kt << 5) + ac * 16;
            CP16(sa, ga);
            CP16(sa + 16, ga + 8);
        } else {
            uint32_t sa = smem_to_u32(Ah + am * APADH + ac * 8);
            const __half* ga = gA + (kt << 5) + ac * 8;
            CP16(sa, ga);
        }
        uint32_t sb = smem_to_u32(Bh + br * BPADH + bc * 8);
        const __half* gb = gB + (size_t)(kt << 5) * N + bc * 8;
        CP16(sb, gb);
        CP16(sb + 16 * BPADH * 2, gb + (size_t)16 * N);
    };

    load_stage(0, 0); CP_COMMIT();
    load_stage(1, 1); CP_COMMIT();
    load_stage(2, 2); CP_COMMIT();

    for (int it = 0; it < NIT; it++) {
        CP_WAIT2();
        __syncthreads();
        if (it + 3 < NIT) load_stage((it + 3) % NSTG, it + 3);
        CP_COMMIT();

        const __half* Ah = smh + (it % NSTG) * STG_H;
        const uint32_t abase = smem_to_u32(Ah);
        const uint32_t bbase = smem_to_u32(Ah + A_ST);
        #pragma unroll
        for (int kk = 0; kk < 2; kk++) {
            uint32_t bfr[4][2];
            #pragma unroll
            for (int ntp = 0; ntp < 2; ntp++) {
                uint32_t addr = bbase +
                    ((kk * 16 + brow) * BPADH + wn * 32 + ntp * 16 + bcol) * 2;
                LDSM4T(bfr[ntp * 2][0], bfr[ntp * 2][1],
                       bfr[ntp * 2 + 1][0], bfr[ntp * 2 + 1][1], addr);
            }
            #pragma unroll
            for (int mt = 0; mt < MTW; mt++) {
                uint32_t af[4];
                uint32_t aaddr = abase +
                    ((wm * (MT / 2) + mt * 16 + arow) * APADH + kk * 16 + acol8) * 2;
                LDSM4(af[0], af[1], af[2], af[3], aaddr);
                #pragma unroll
                for (int nt = 0; nt < 4; nt++)
                    mma1616(acc[mt][nt], af, bfr[nt]);
            }
        }
    }

    #pragma unroll
    for (int mt = 0; mt < MTW; mt++) {
        #pragma unroll
        for (int nt = 0; nt < 4; nt++) {
            int col = bn + wn * 32 + nt * 8 + lc * 2;
            float2 bv = *(const float2*)(bias + col);
            #pragma unroll
            for (int half = 0; half < 2; half++) {
                size_t row = (size_t)(bm + wm * (MT / 2) + mt * 16 + lr + half * 8);
                float v0 = acc[mt][nt][half * 2 + 0] + bv.x;
                float v1 = acc[mt][nt][half * 2 + 1] + bv.y;
                if (EPI == EPI_BIAS_RES) {
                    float2 rv = *(const float2*)(R + row * N + col);
                    v0 += rv.x; v1 += rv.y;
                }
                if (EPI == EPI_BIAS_GELU) {
                    v0 = 0.5f * v0 * (1.f + erff(v0 * 0.7071067811865476f));
                    v1 = 0.5f * v1 * (1.f + erff(v1 * 0.7071067811865476f));
                }
                if (OUTH) {
                    *(__half2*)(Ch + row * N + col) = __floats2half2_rn(v0, v1);
                } else {
                    float2 o = {v0, v1};
                    *(float2*)(Cf + row * N + col) = o;
                }
            }
        }
    }
}

// ---------------- all weights fp32 -> fp16, one launch ---------------------------
#define N4_0 (768 * 2304 / 4)
#define N4_1 (768 * 768 / 4)
#define N4_2 (768 * 3072 / 4)
#define N4_3 (3072 * 768 / 4)
#define N4_ALL (N4_0 + N4_1 + N4_2 + N4_3)

__global__ void cvt_all(const float4* __restrict__ w0, const float4* __restrict__ w1,
                        const float4* __restrict__ w2, const float4* __restrict__ w3,
                        __half2* __restrict__ o0, __half2* __restrict__ o1,
                        __half2* __restrict__ o2, __half2* __restrict__ o3) {
    int i = blockIdx.x * 256 + threadIdx.x;
    const float4* src;
    __half2* dst;
    int j = i;
    if (j < N4_0)                { src = w0; dst = o0; }
    else if ((j -= N4_0) < N4_1) { src = w1; dst = o1; }
    else if ((j -= N4_1) < N4_2) { src = w2; dst = o2; }
    else if ((j -= N4_2) < N4_3) { src = w3; dst = o3; }
    else return;
    float4 v = src[j];
    dst[j * 2]     = __floats2half2_rn(v.x, v.y);
    dst[j * 2 + 1] = __floats2half2_rn(v.z, v.w);
}

// ---------------- LayerNorm: warp per row, shfl-only reductions -------------------
__global__ void __launch_bounds__(256) ln_kernel(
    const float* __restrict__ x, const float* __restrict__ w,
    const float* __restrict__ bb, __half* __restrict__ y)
{
    const int warp = threadIdx.x >> 5, lane = threadIdx.x & 31;
    const size_t row = (size_t)blockIdx.x * 8 + warp;
    const float* xr = x + row * D_;

    float4 v[6];
    float s = 0.f;
    #pragma unroll
    for (int i = 0; i < 6; i++) {
        v[i] = *(const float4*)(xr + (i * 32 + lane) * 4);
        s += v[i].x + v[i].y + v[i].z + v[i].w;
    }
    #pragma unroll
    for (int o = 16; o > 0; o >>= 1) s += __shfl_xor_sync(0xffffffffu, s, o);
    const float mu = s * (1.f / 768.f);

    float vs = 0.f;
    #pragma unroll
    for (int i = 0; i < 6; i++) {
        v[i].x -= mu; v[i].y -= mu; v[i].z -= mu; v[i].w -= mu;
        vs += v[i].x * v[i].x + v[i].y * v[i].y + v[i].z * v[i].z + v[i].w * v[i].w;
    }
    #pragma unroll
    for (int o = 16; o > 0; o >>= 1) vs += __shfl_xor_sync(0xffffffffu, vs, o);
    const float rstd = rsqrtf(vs * (1.f / 768.f) + 1e-5f);

    __half* yr = y + row * D_;
    #pragma unroll
    for (int i = 0; i < 6; i++) {
        int c = (i * 32 + lane) * 4;
        float4 wv = *(const float4*)(w + c);
        float4 bv = *(const float4*)(bb + c);
        __half2 h0 = __floats2half2_rn(v[i].x * rstd * wv.x + bv.x,
                                       v[i].y * rstd * wv.y + bv.y);
        __half2 h1 = __floats2half2_rn(v[i].z * rstd * wv.z + bv.z,
                                       v[i].w * rstd * wv.w + bv.w);
        uint2 pack = {h2u(h0), h2u(h1)};
        *(uint2*)(yr + c) = pack;
    }
}

// ---------------- Attention: fp16 tensor-core flash, windowed causal -------------
#define TQ 128
#define QPH 72
#define KPH 72
#define VPH 72
#define ATTN_SMEM_BYTES ((128 * QPH + 64 * KPH + 64 * VPH) * 2 + 256 + 16)

__global__ void __launch_bounds__(256, 2) attn_h_kernel(
    const __half* __restrict__ qkv, const int* __restrict__ amask,
    __half* __restrict__ out)
{
    extern __shared__ char dynsm[];
    __half* Qs = (__half*)dynsm;
    __half* Kn = Qs + 128 * QPH;
    __half* Vs = Kn + 64 * KPH;
    int* kmsk = (int*)(Vs + 64 * VPH);
    int* mflag = kmsk + 64;

    const int qi = blockIdx.x, h = blockIdx.y, b = blockIdx.z;
    const int qb = qi * TQ;
    const int tid = threadIdx.x, wid = tid >> 5, lane = tid & 31;
    const int lr = lane >> 2, lc = lane & 3;
    const int wq = wid * 16;
    const int sel = lane >> 3;
    const int vrow = (sel & 1) * 8 + (lane & 7);
    const int vcol = (sel >> 1) * 8;
    const int krow = (lane & 7) + ((lane >> 4) << 3);
    const int kcol = ((lane >> 3) & 1) * 8;

    {
        int r = tid >> 1, cb = (tid & 1) * 32;
        const __half* src = qkv + (size_t)(b * T_ + qb + r) * (3 * D_) + h * 64 + cb;
        #pragma unroll
        for (int c = 0; c < 4; c++)
            *(uint4*)(Qs + r * QPH + cb + c * 8) = *(const uint4*)(src + c * 8);
    }
    __syncthreads();
    const __half2 sc2 = __floats2half2_rn(0.125f, 0.125f);
    uint32_t qa[4][4];
    #pragma unroll
    for (int kk = 0; kk < 4; kk++) {
        const __half* p = Qs + (size_t)(wq + lr) * QPH + kk * 16 + lc * 2;
        qa[kk][0] = h2u(__hmul2(*(const __half2*)p, sc2));
        qa[kk][1] = h2u(__hmul2(*(const __half2*)(p + 8 * QPH), sc2));
        qa[kk][2] = h2u(__hmul2(*(const __half2*)(p + 8), sc2));
        qa[kk][3] = h2u(__hmul2(*(const __half2*)(p + 8 * QPH + 8), sc2));
    }

    float o[8][4];
    #pragma unroll
    for (int j = 0; j < 8; j++)
        #pragma unroll
        for (int k = 0; k < 4; k++) o[j][k] = 0.f;
    float mrow[2] = {-1e30f, -1e30f}, lrow[2] = {0.f, 0.f};

    int lo = qb - (WIN_ - 1);
    const int kt0 = (lo > 0 ? lo : 0) >> 6;
    const int kt1 = (qb + TQ - 1) >> 6;

    for (int kt = kt0; kt <= kt1; kt++) {
        const int kb = kt * 64;
        __syncthreads();
        {
            int r = tid >> 2, cb = (tid & 3) * 16;
            const __half* kp = qkv + (size_t)(b * T_ + kb + r) * (3 * D_) + D_ + h * 64 + cb;
            *(uint4*)(Kn + r * KPH + cb)     = *(const uint4*)kp;
            *(uint4*)(Kn + r * KPH + cb + 8) = *(const uint4*)(kp + 8);
            *(uint4*)(Vs + r * VPH + cb)     = *(const uint4*)(kp + D_);
            *(uint4*)(Vs + r * VPH + cb + 8) = *(const uint4*)(kp + D_ + 8);
            if (tid < 64) {
                int mv = amask[b * T_ + kb + tid];
                kmsk[tid] = mv;
                unsigned bal = __ballot_sync(0xffffffffu, mv != 0);
                if ((tid & 31) == 0) mflag[tid >> 5] = (bal == 0xffffffffu);
            }
        }
        __syncthreads();

        const bool tilefull = (kb + 63 <= qb) && (kb >= qb - 640) &&
                              mflag[0] && mflag[1];

        float s[8][4];
        #pragma unroll
        for (int j = 0; j < 8; j++)
            s[j][0] = s[j][1] = s[j][2] = s[j][3] = 0.f;
        const uint32_t kbase = smem_to_u32(Kn);
        #pragma unroll
        for (int jp = 0; jp < 4; jp++) {
            #pragma unroll
            for (int kk = 0; kk < 4; kk++) {
                uint32_t kb4[4];
                uint32_t addr = kbase + ((jp * 16 + krow) * KPH + kk * 16 + kcol) * 2;
                LDSM4(kb4[0], kb4[1], kb4[2], kb4[3], addr);
                mma1616(s[jp * 2],     qa[kk], kb4);
                mma1616(s[jp * 2 + 1], qa[kk], kb4 + 2);
            }
        }

        if (!tilefull) {
            #pragma unroll
            for (int j = 0; j < 8; j++) {
                int kg0 = kb + j * 8 + lc * 2, kg1 = kg0 + 1;
                int km0 = kmsk[j * 8 + lc * 2], km1 = kmsk[j * 8 + lc * 2 + 1];
                #pragma unroll
                for (int half = 0; half < 2; half++) {
                    int qg = qb + wq + lr + half * 8;
                    bool v0 = (kg0 <= qg) && (kg0 > qg - WIN_) && (km0 != 0);
                    bool v1 = (kg1 <= qg) && (kg1 > qg - WIN_) && (km1 != 0);
                    if (!v0) s[j][half * 2 + 0] = -1e30f;
                    if (!v1) s[j][half * 2 + 1] = -1e30f;
                }
            }
        }

        float mnew[2], alpha[2], lsum[2];
        #pragma unroll
        for (int half = 0; half < 2; half++) {
            float m = -1e30f;
            #pragma unroll
            for (int j = 0; j < 8; j++)
                m = fmaxf(m, fmaxf(s[j][half * 2], s[j][half * 2 + 1]));
            m = fmaxf(m, __shfl_xor_sync(0xffffffffu, m, 1));
            m = fmaxf(m, __shfl_xor_sync(0xffffffffu, m, 2));
            mnew[half] = fmaxf(mrow[half], m);
            alpha[half] = __expf(mrow[half] - mnew[half]);
            lsum[half] = 0.f;
        }
        if (tilefull) {
            #pragma unroll
            for (int j = 0; j < 8; j++) {
                #pragma unroll
                for (int half = 0; half < 2; half++) {
                    float p0 = __expf(s[j][half * 2]     - mnew[half]);
                    float p1 = __expf(s[j][half * 2 + 1] - mnew[half]);
                    s[j][half * 2] = p0; s[j][half * 2 + 1] = p1;
                    lsum[half] += p0 + p1;
                }
            }
        } else {
            #pragma unroll
            for (int j = 0; j < 8; j++) {
                #pragma unroll
                for (int half = 0; half < 2; half++) {
                    float s0 = s[j][half * 2], s1 = s[j][half * 2 + 1];
                    float p0 = (s0 <= -1e29f) ? 0.f : __expf(s0 - mnew[half]);
                    float p1 = (s1 <= -1e29f) ? 0.f : __expf(s1 - mnew[half]);
                    s[j][half * 2] = p0; s[j][half * 2 + 1] = p1;
                    lsum[half] += p0 + p1;
                }
            }
        }
        #pragma unroll
        for (int half = 0; half < 2; half++) {
            lsum[half] += __shfl_xor_sync(0xffffffffu, lsum[half], 1);
            lsum[half] += __shfl_xor_sync(0xffffffffu, lsum[half], 2);
            lrow[half] = lrow[half] * alpha[half] + lsum[half];
            mrow[half] = mnew[half];
        }
        #pragma unroll
        for (int j = 0; j < 8; j++) {
            o[j][0] *= alpha[0]; o[j][1] *= alpha[0];
            o[j][2] *= alpha[1]; o[j][3] *= alpha[1];
        }

        const uint32_t vbase = smem_to_u32(Vs);
        #pragma unroll
        for (int kk = 0; kk < 4; kk++) {
            uint32_t pa[4] = {
                h2u(__floats2half2_rn(s[2 * kk][0],     s[2 * kk][1])),
                h2u(__floats2half2_rn(s[2 * kk][2],     s[2 * kk][3])),
                h2u(__floats2half2_rn(s[2 * kk + 1][0], s[2 * kk + 1][1])),
                h2u(__floats2half2_rn(s[2 * kk + 1][2], s[2 * kk + 1][3]))
            };
            #pragma unroll
            for (int jp = 0; jp < 4; jp++) {
                uint32_t vb[4];
                uint32_t addr = vbase + ((kk * 16 + vrow) * VPH + jp * 16 + vcol) * 2;
                LDSM4T(vb[0], vb[1], vb[2], vb[3], addr);
                mma1616(o[jp * 2],     pa, vb);
                mma1616(o[jp * 2 + 1], pa, vb + 2);
            }
        }
    }

    float linv[2] = {1.f / lrow[0], 1.f / lrow[1]};
    #pragma unroll
    for (int half = 0; half < 2; half++) {
        size_t row = (size_t)(b * T_ + qb + wq + lr + half * 8);
        __half* op = out + row * D_ + h * 64;
        #pragma unroll
        for (int j = 0; j < 8; j++)
            *(__half2*)(op + j * 8 + lc * 2) =
                __floats2half2_rn(o[j][half * 2] * linv[half], o[j][half * 2 + 1] * linv[half]);
    }
}

// ---------------- launch -----------------------------------------------------------
extern "C" void kernel_launch(void* const* d_in, const int* in_sizes, int n_in,
                              void* d_out, int out_size)
{
    const float* x      = (const float*)d_in[0];
    const int*   amask  = (const int*)d_in[1];
    const float* ln1_w  = (const float*)d_in[2];
    const float* ln1_b  = (const float*)d_in[3];
    const float* w_attn = (const float*)d_in[4];
    const float* b_attn = (const float*)d_in[5];
    const float* w_proj = (const float*)d_in[6];
    const float* b_proj = (const float*)d_in[7];
    const float* ln2_w  = (const float*)d_in[8];
    const float* ln2_b  = (const float*)d_in[9];
    const float* w_fc   = (const float*)d_in[10];
    const float* b_fc   = (const float*)d_in[11];
    const float* w_fcp  = (const float*)d_in[12];
    const float* b_fcp  = (const float*)d_in[13];
    float* out = (float*)d_out;

    __half *p_x1h, *p_qkvh, *p_attnh, *p_hh, *p_wah, *p_wph, *p_wfh, *p_wfph;
    float* p_x2;
    cudaGetSymbolAddress((void**)&p_x1h,   g_x1h);
    cudaGetSymbolAddress((void**)&p_qkvh,  g_qkvh);
    cudaGetSymbolAddress((void**)&p_attnh, g_attnh);
    cudaGetSymbolAddress((void**)&p_x2,    g_x2);
    cudaGetSymbolAddress((void**)&p_hh,    g_hh);
    cudaGetSymbolAddress((void**)&p_wah,   g_wah);
    cudaGetSymbolAddress((void**)&p_wph,   g_wph);
    cudaGetSymbolAddress((void**)&p_wfh,   g_wfh);
    cudaGetSymbolAddress((void**)&p_wfph,  g_wfph);

    cudaFuncSetAttribute((const void*)hgemm<EPI_BIAS, true, 128>,
                         cudaFuncAttributeMaxDynamicSharedMemorySize, GEMM_SMEM_MT(128));
    cudaFuncSetAttribute((const void*)hgemm<EPI_BIAS_GELU, true, 128>,
                         cudaFuncAttributeMaxDynamicSharedMemorySize, GEMM_SMEM_MT(128));
    cudaFuncSetAttribute((const void*)hgemm<EPI_BIAS_RES, false, 64>,
                         cudaFuncAttributeMaxDynamicSharedMemorySize, GEMM_SMEM_MT(64));
    cudaFuncSetAttribute(attn_h_kernel, cudaFuncAttributeMaxDynamicSharedMemorySize, ATTN_SMEM_BYTES);

    cvt_all<<<(N4_ALL + 255) / 256, 256>>>(
        (const float4*)w_attn, (const float4*)w_proj, (const float4*)w_fc, (const float4*)w_fcp,
        (__half2*)p_wah, (__half2*)p_wph, (__half2*)p_wfh, (__half2*)p_wfph);

    // 1) ln1 -> fp16
    ln_kernel<<<M_ / 8, 256>>>(x, ln1_w, ln1_b, p_x1h);
    // 2) qkv = x1 @ w_attn + b_attn   (128-tile, 3.9 waves)
    hgemm<EPI_BIAS, true, 128><<<dim3(2304 / 128, M_ / 128), 256, GEMM_SMEM_MT(128)>>>(
        p_x1h, p_wah, b_attn, nullptr, nullptr, p_qkvh, 2304, 768);
    // 3) attention
    attn_h_kernel<<<dim3(T_ / TQ, H_, B_), 256, ATTN_SMEM_BYTES>>>(p_qkvh, amask, p_attnh);
    // 4) x2 = attn @ w_proj + b_proj + x   (64-tile vs wave quantization)
    hgemm<EPI_BIAS_RES, false, 64><<<dim3(768 / 128, M_ / 64), 256, GEMM_SMEM_MT(64)>>>(
        p_attnh, p_wph, b_proj, x, p_x2, nullptr, 768, 768);
    // 5) ln2 -> fp16
    ln_kernel<<<M_ / 8, 256>>>(p_x2, ln2_w, ln2_b, p_x1h);
    // 6) h = gelu(x1 @ w_fc + b_fc)   (128-tile, 5.2 waves)
    hgemm<EPI_BIAS_GELU, true, 128><<<dim3(3072 / 128, M_ / 128), 256, GEMM_SMEM_MT(128)>>>(
        p_x1h, p_wfh, b_fc, nullptr, nullptr, p_hh, 3072, 768);
    // 7) out = h @ w_fc_proj + b_fc_proj + x2   (64-tile vs wave quantization)
    hgemm<EPI_BIAS_RES, false, 64><<<dim3(768 / 128, M_ / 64), 256, GEMM_SMEM_MT(64)>>>(
        p_hh, p_wfph, b_fcp, p_x2, out, nullptr, 768, 3072);
}

// round 10
// speedup vs baseline: 1.0479x; 1.0036x over previous
#include <cuda_runtime.h>
#include <cuda_fp16.h>
#include <math.h>
#include <stdint.h>

#define B_   8
#define T_   1024
#define D_   768
#define H_   12
#define WIN_ 768
#define M_   (B_*T_)   // 8192

// ---------------- scratch (static device globals) ---------------------------
__device__ __half g_x1h[M_ * D_];
__device__ __half g_qkvh[M_ * 3 * D_];
__device__ __half g_attnh[M_ * D_];
__device__ float  g_x2[M_ * D_];
__device__ __half g_hh[M_ * 4 * D_];
__device__ __half g_wah[D_ * 3 * D_];
__device__ __half g_wph[D_ * D_];
__device__ __half g_wfh[D_ * 4 * D_];
__device__ __half g_wfph[4 * D_ * D_];

// ---------------- helpers -----------------------------------------------------
__device__ __forceinline__ uint32_t smem_to_u32(const void* p) {
    uint32_t a;
    asm("{ .reg .u64 t; cvta.to.shared.u64 t, %1; cvt.u32.u64 %0, t; }" : "=r"(a) : "l"(p));
    return a;
}
__device__ __forceinline__ uint32_t h2u(__half2 v) { return *(uint32_t*)&v; }

#define CP16(saddr, gptr) \
    asm volatile("cp.async.cg.shared.global [%0], [%1], 16;" :: "r"(saddr), "l"(gptr))
#define CP_COMMIT() asm volatile("cp.async.commit_group;" ::: "memory")
#define CP_WAIT2()  asm volatile("cp.async.wait_group 2;" ::: "memory")
#define CP_WAIT1()  asm volatile("cp.async.wait_group 1;" ::: "memory")

#define LDSM4(r0, r1, r2, r3, addr) \
    asm volatile("ldmatrix.sync.aligned.m8n8.x4.shared.b16 {%0,%1,%2,%3}, [%4];" \
        : "=r"(r0), "=r"(r1), "=r"(r2), "=r"(r3) : "r"(addr))
#define LDSM4T(r0, r1, r2, r3, addr) \
    asm volatile("ldmatrix.sync.aligned.m8n8.x4.trans.shared.b16 {%0,%1,%2,%3}, [%4];" \
        : "=r"(r0), "=r"(r1), "=r"(r2), "=r"(r3) : "r"(addr))

__device__ __forceinline__ void mma1616(float* d, const uint32_t* a, const uint32_t* b) {
    asm volatile(
        "mma.sync.aligned.m16n8k16.row.col.f32.f16.f16.f32 "
        "{%0,%1,%2,%3}, {%4,%5,%6,%7}, {%8,%9}, {%0,%1,%2,%3};"
        : "+f"(d[0]), "+f"(d[1]), "+f"(d[2]), "+f"(d[3])
        : "r"(a[0]), "r"(a[1]), "r"(a[2]), "r"(a[3]), "r"(b[0]), "r"(b[1]));
}

// ---------------- fp16 tensor-core GEMM (round-8 config: 128x128) ---------------
enum { EPI_BIAS = 0, EPI_BIAS_RES = 1, EPI_BIAS_GELU = 2 };

#define NSTG 4
#define APADH 40
#define BPADH 136
#define A_ST (128 * APADH)
#define B_ST (32 * BPADH)
#define STG_H (A_ST + B_ST)
#define GEMM_SMEM (NSTG * STG_H * 2)

template <int EPI, bool OUTH>
__global__ void __launch_bounds__(256, 2) hgemm(
    const __half* __restrict__ A, const __half* __restrict__ W,
    const float* __restrict__ bias, const float* __restrict__ R,
    float* __restrict__ Cf, __half* __restrict__ Ch, int N, int K)
{
    extern __shared__ char dynsm[];
    __half* smh = (__half*)dynsm;
    const int tid = threadIdx.x;
    const int wid = tid >> 5, lane = tid & 31;
    const int wm = wid >> 2, wn = wid & 3;
    const int bm = blockIdx.y << 7, bn = blockIdx.x << 7;
    const int lr = lane >> 2, lc = lane & 3;
    const int arow = lane & 15, acol8 = (lane >> 4) * 8;
    const int sel = lane >> 3;
    const int brow = (sel & 1) * 8 + (lane & 7), bcol = (sel >> 1) * 8;
    const int NIT = K >> 5;

    const int am = tid >> 1, ac = tid & 1;
    const int br = tid >> 4, bc = tid & 15;
    const __half* gA = A + (size_t)(bm + am) * K;
    const __half* gB = W + (size_t)br * N + bn;

    float acc[4][4][4];
    #pragma unroll
    for (int i = 0; i < 4; i++)
        #pragma unroll
        for (int j = 0; j < 4; j++)
            #pragma unroll
            for (int k = 0; k < 4; k++) acc[i][j][k] = 0.f;

    auto load_stage = [&](int s, int kt) {
        __half* Ah = smh + s * STG_H;
        __half* Bh = Ah + A_ST;
        uint32_t sa = smem_to_u32(Ah + am * APADH + ac * 16);
        const __half* ga = gA + (kt << 5) + ac * 16;
        CP16(sa, ga);
        CP16(sa + 16, ga + 8);
        uint32_t sb = smem_to_u32(Bh + br * BPADH + bc * 8);
        const __half* gb = gB + (size_t)(kt << 5) * N + bc * 8;
        CP16(sb, gb);
        CP16(sb + 16 * BPADH * 2, gb + (size_t)16 * N);
    };

    load_stage(0, 0); CP_COMMIT();
    load_stage(1, 1); CP_COMMIT();
    load_stage(2, 2); CP_COMMIT();

    for (int it = 0; it < NIT; it++) {
        CP_WAIT2();
        __syncthreads();
        if (it + 3 < NIT) load_stage((it + 3) % NSTG, it + 3);
        CP_COMMIT();

        const __half* Ah = smh + (it % NSTG) * STG_H;
        const uint32_t abase = smem_to_u32(Ah);
        const uint32_t bbase = smem_to_u32(Ah + A_ST);
        #pragma unroll
        for (int kk = 0; kk < 2; kk++) {
            uint32_t bfr[4][2];
            #pragma unroll
            for (int ntp = 0; ntp < 2; ntp++) {
                uint32_t addr = bbase +
                    ((kk * 16 + brow) * BPADH + wn * 32 + ntp * 16 + bcol) * 2;
                LDSM4T(bfr[ntp * 2][0], bfr[ntp * 2][1],
                       bfr[ntp * 2 + 1][0], bfr[ntp * 2 + 1][1], addr);
            }
            #pragma unroll
            for (int mt = 0; mt < 4; mt++) {
                uint32_t af[4];
                uint32_t aaddr = abase +
                    ((wm * 64 + mt * 16 + arow) * APADH + kk * 16 + acol8) * 2;
                LDSM4(af[0], af[1], af[2], af[3], aaddr);
                #pragma unroll
                for (int nt = 0; nt < 4; nt++)
                    mma1616(acc[mt][nt], af, bfr[nt]);
            }
        }
    }

    #pragma unroll
    for (int mt = 0; mt < 4; mt++) {
        #pragma unroll
        for (int nt = 0; nt < 4; nt++) {
            int col = bn + wn * 32 + nt * 8 + lc * 2;
            float2 bv = *(const float2*)(bias + col);
            #pragma unroll
            for (int half = 0; half < 2; half++) {
                size_t row = (size_t)(bm + wm * 64 + mt * 16 + lr + half * 8);
                float v0 = acc[mt][nt][half * 2 + 0] + bv.x;
                float v1 = acc[mt][nt][half * 2 + 1] + bv.y;
                if (EPI == EPI_BIAS_RES) {
                    float2 rv = *(const float2*)(R + row * N + col);
                    v0 += rv.x; v1 += rv.y;
                }
                if (EPI == EPI_BIAS_GELU) {
                    v0 = 0.5f * v0 * (1.f + erff(v0 * 0.7071067811865476f));
                    v1 = 0.5f * v1 * (1.f + erff(v1 * 0.7071067811865476f));
                }
                if (OUTH) {
                    *(__half2*)(Ch + row * N + col) = __floats2half2_rn(v0, v1);
                } else {
                    float2 o = {v0, v1};
                    *(float2*)(Cf + row * N + col) = o;
                }
            }
        }
    }
}

// ---------------- all weights fp32 -> fp16, one launch ---------------------------
#define N4_0 (768 * 2304 / 4)
#define N4_1 (768 * 768 / 4)
#define N4_2 (768 * 3072 / 4)
#define N4_3 (3072 * 768 / 4)
#define N4_ALL (N4_0 + N4_1 + N4_2 + N4_3)

__global__ void cvt_all(const float4* __restrict__ w0, const float4* __restrict__ w1,
                        const float4* __restrict__ w2, const float4* __restrict__ w3,
                        __half2* __restrict__ o0, __half2* __restrict__ o1,
                        __half2* __restrict__ o2, __half2* __restrict__ o3) {
    int i = blockIdx.x * 256 + threadIdx.x;
    const float4* src;
    __half2* dst;
    int j = i;
    if (j < N4_0)                { src = w0; dst = o0; }
    else if ((j -= N4_0) < N4_1) { src = w1; dst = o1; }
    else if ((j -= N4_1) < N4_2) { src = w2; dst = o2; }
    else if ((j -= N4_2) < N4_3) { src = w3; dst = o3; }
    else return;
    float4 v = src[j];
    dst[j * 2]     = __floats2half2_rn(v.x, v.y);
    dst[j * 2 + 1] = __floats2half2_rn(v.z, v.w);
}

// ---------------- LayerNorm: warp per row, shfl-only reductions -------------------
__global__ void __launch_bounds__(256) ln_kernel(
    const float* __restrict__ x, const float* __restrict__ w,
    const float* __restrict__ bb, __half* __restrict__ y)
{
    const int warp = threadIdx.x >> 5, lane = threadIdx.x & 31;
    const size_t row = (size_t)blockIdx.x * 8 + warp;
    const float* xr = x + row * D_;

    float4 v[6];
    float s = 0.f;
    #pragma unroll
    for (int i = 0; i < 6; i++) {
        v[i] = *(const float4*)(xr + (i * 32 + lane) * 4);
        s += v[i].x + v[i].y + v[i].z + v[i].w;
    }
    #pragma unroll
    for (int o = 16; o > 0; o >>= 1) s += __shfl_xor_sync(0xffffffffu, s, o);
    const float mu = s * (1.f / 768.f);

    float vs = 0.f;
    #pragma unroll
    for (int i = 0; i < 6; i++) {
        v[i].x -= mu; v[i].y -= mu; v[i].z -= mu; v[i].w -= mu;
        vs += v[i].x * v[i].x + v[i].y * v[i].y + v[i].z * v[i].z + v[i].w * v[i].w;
    }
    #pragma unroll
    for (int o = 16; o > 0; o >>= 1) vs += __shfl_xor_sync(0xffffffffu, vs, o);
    const float rstd = rsqrtf(vs * (1.f / 768.f) + 1e-5f);

    __half* yr = y + row * D_;
    #pragma unroll
    for (int i = 0; i < 6; i++) {
        int c = (i * 32 + lane) * 4;
        float4 wv = *(const float4*)(w + c);
        float4 bv = *(const float4*)(bb + c);
        __half2 h0 = __floats2half2_rn(v[i].x * rstd * wv.x + bv.x,
                                       v[i].y * rstd * wv.y + bv.y);
        __half2 h1 = __floats2half2_rn(v[i].z * rstd * wv.z + bv.z,
                                       v[i].w * rstd * wv.w + bv.w);
        uint2 pack = {h2u(h0), h2u(h1)};
        *(uint2*)(yr + c) = pack;
    }
}

// ---------------- Attention: fp16 TC flash + cp.async K/V pipeline ----------------
// q-tile 128, key-tile 64, 3-slot cp.async pipeline over K/V(+mask) tiles.
#define TQ 128
#define QPH 72
#define KPH 72
#define VPH 72
#define KV_SLOT (64 * KPH + 64 * VPH)     // halves per slot
#define ATTN_SMEM_BYTES ((128 * QPH + 3 * KV_SLOT) * 2 + 3 * 64 * 4 + 3 * 2 * 4 + 32)

__global__ void __launch_bounds__(256, 2) attn_h_kernel(
    const __half* __restrict__ qkv, const int* __restrict__ amask,
    __half* __restrict__ out)
{
    extern __shared__ char dynsm[];
    __half* Qs = (__half*)dynsm;                     // [128][QPH]
    __half* KV = Qs + 128 * QPH;                     // 3 slots of (K[64][KPH], V[64][VPH])
    int* kmsk  = (int*)(KV + 3 * KV_SLOT);           // [3][64]
    int* mflag = kmsk + 3 * 64;                      // [3][2]

    const int qi = blockIdx.x, h = blockIdx.y, b = blockIdx.z;
    const int qb = qi * TQ;
    const int tid = threadIdx.x, wid = tid >> 5, lane = tid & 31;
    const int lr = lane >> 2, lc = lane & 3;
    const int wq = wid * 16;
    const int sel = lane >> 3;
    const int vrow = (sel & 1) * 8 + (lane & 7);
    const int vcol = (sel >> 1) * 8;
    const int krow = (lane & 7) + ((lane >> 4) << 3);
    const int kcol = ((lane >> 3) & 1) * 8;

    // stage Q (synchronous, once)
    {
        int r = tid >> 1, cb = (tid & 1) * 32;
        const __half* src = qkv + (size_t)(b * T_ + qb + r) * (3 * D_) + h * 64 + cb;
        #pragma unroll
        for (int c = 0; c < 4; c++)
            *(uint4*)(Qs + r * QPH + cb + c * 8) = *(const uint4*)(src + c * 8);
    }

    int lo = qb - (WIN_ - 1);
    const int kt0 = (lo > 0 ? lo : 0) >> 6;
    const int kt1 = (qb + TQ - 1) >> 6;

    // K/V tile loader into slot s (cp.async) + mask (regular store)
    const int lrr = tid >> 2, lcb = (tid & 3) * 16;
    auto load_kv = [&](int s, int kt) {
        const int kb = kt * 64;
        __half* Kb = KV + s * KV_SLOT;
        __half* Vb = Kb + 64 * KPH;
        const __half* kp = qkv + (size_t)(b * T_ + kb + lrr) * (3 * D_) + D_ + h * 64 + lcb;
        uint32_t ka = smem_to_u32(Kb + lrr * KPH + lcb);
        uint32_t va = smem_to_u32(Vb + lrr * VPH + lcb);
        CP16(ka, kp);           CP16(ka + 16, kp + 8);
        CP16(va, kp + D_);      CP16(va + 16, kp + D_ + 8);
        if (tid < 64) {
            int mv = amask[b * T_ + kb + tid];
            kmsk[s * 64 + tid] = mv;
            unsigned bal = __ballot_sync(0xffffffffu, mv != 0);
            if ((tid & 31) == 0) mflag[s * 2 + (tid >> 5)] = (bal == 0xffffffffu);
        }
    };

    // prologue: 2 tiles in flight
    load_kv(0, kt0); CP_COMMIT();
    if (kt0 + 1 <= kt1) load_kv(1, kt0 + 1);
    CP_COMMIT();

    __syncthreads();   // Q visible to all (and prologue mask stores ordered)
    const __half2 sc2 = __floats2half2_rn(0.125f, 0.125f);
    uint32_t qa[4][4];
    #pragma unroll
    for (int kk = 0; kk < 4; kk++) {
        const __half* p = Qs + (size_t)(wq + lr) * QPH + kk * 16 + lc * 2;
        qa[kk][0] = h2u(__hmul2(*(const __half2*)p, sc2));
        qa[kk][1] = h2u(__hmul2(*(const __half2*)(p + 8 * QPH), sc2));
        qa[kk][2] = h2u(__hmul2(*(const __half2*)(p + 8), sc2));
        qa[kk][3] = h2u(__hmul2(*(const __half2*)(p + 8 * QPH + 8), sc2));
    }

    float o[8][4];
    #pragma unroll
    for (int j = 0; j < 8; j++)
        #pragma unroll
        for (int k = 0; k < 4; k++) o[j][k] = 0.f;
    float mrow[2] = {-1e30f, -1e30f}, lrow[2] = {0.f, 0.f};

    for (int kt = kt0; kt <= kt1; kt++) {
        const int kb = kt * 64;
        const int s = (kt - kt0) % 3;

        CP_WAIT1();          // slot s's group complete (1 group may remain in flight)
        __syncthreads();     // cp.async data + mask stores visible; slot (kt+2)%3 free
        if (kt + 2 <= kt1) load_kv((kt - kt0 + 2) % 3, kt + 2);
        CP_COMMIT();

        const __half* Kb = KV + s * KV_SLOT;
        const __half* Vb = Kb + 64 * KPH;
        const int* km = kmsk + s * 64;
        const bool tilefull = (kb + 63 <= qb) && (kb >= qb - 640) &&
                              mflag[s * 2] && mflag[s * 2 + 1];

        float sv[8][4];
        #pragma unroll
        for (int j = 0; j < 8; j++)
            sv[j][0] = sv[j][1] = sv[j][2] = sv[j][3] = 0.f;
        const uint32_t kbase = smem_to_u32(Kb);
        #pragma unroll
        for (int jp = 0; jp < 4; jp++) {
            #pragma unroll
            for (int kk = 0; kk < 4; kk++) {
                uint32_t kb4[4];
                uint32_t addr = kbase + ((jp * 16 + krow) * KPH + kk * 16 + kcol) * 2;
                LDSM4(kb4[0], kb4[1], kb4[2], kb4[3], addr);
                mma1616(sv[jp * 2],     qa[kk], kb4);
                mma1616(sv[jp * 2 + 1], qa[kk], kb4 + 2);
            }
        }

        if (!tilefull) {
            #pragma unroll
            for (int j = 0; j < 8; j++) {
                int kg0 = kb + j * 8 + lc * 2, kg1 = kg0 + 1;
                int km0 = km[j * 8 + lc * 2], km1 = km[j * 8 + lc * 2 + 1];
                #pragma unroll
                for (int half = 0; half < 2; half++) {
                    int qg = qb + wq + lr + half * 8;
                    bool v0 = (kg0 <= qg) && (kg0 > qg - WIN_) && (km0 != 0);
                    bool v1 = (kg1 <= qg) && (kg1 > qg - WIN_) && (km1 != 0);
                    if (!v0) sv[j][half * 2 + 0] = -1e30f;
                    if (!v1) sv[j][half * 2 + 1] = -1e30f;
                }
            }
        }

        float mnew[2], alpha[2], lsum[2];
        #pragma unroll
        for (int half = 0; half < 2; half++) {
            float m = -1e30f;
            #pragma unroll
            for (int j = 0; j < 8; j++)
                m = fmaxf(m, fmaxf(sv[j][half * 2], sv[j][half * 2 + 1]));
            m = fmaxf(m, __shfl_xor_sync(0xffffffffu, m, 1));
            m = fmaxf(m, __shfl_xor_sync(0xffffffffu, m, 2));
            mnew[half] = fmaxf(mrow[half], m);
            alpha[half] = __expf(mrow[half] - mnew[half]);
            lsum[half] = 0.f;
        }
        if (tilefull) {
            #pragma unroll
            for (int j = 0; j < 8; j++) {
                #pragma unroll
                for (int half = 0; half < 2; half++) {
                    float p0 = __expf(sv[j][half * 2]     - mnew[half]);
                    float p1 = __expf(sv[j][half * 2 + 1] - mnew[half]);
                    sv[j][half * 2] = p0; sv[j][half * 2 + 1] = p1;
                    lsum[half] += p0 + p1;
                }
            }
        } else {
            #pragma unroll
            for (int j = 0; j < 8; j++) {
                #pragma unroll
                for (int half = 0; half < 2; half++) {
                    float s0 = sv[j][half * 2], s1 = sv[j][half * 2 + 1];
                    float p0 = (s0 <= -1e29f) ? 0.f : __expf(s0 - mnew[half]);
                    float p1 = (s1 <= -1e29f) ? 0.f : __expf(s1 - mnew[half]);
                    sv[j][half * 2] = p0; sv[j][half * 2 + 1] = p1;
                    lsum[half] += p0 + p1;
                }
            }
        }
        #pragma unroll
        for (int half = 0; half < 2; half++) {
            lsum[half] += __shfl_xor_sync(0xffffffffu, lsum[half], 1);
            lsum[half] += __shfl_xor_sync(0xffffffffu, lsum[half], 2);
            lrow[half] = lrow[half] * alpha[half] + lsum[half];
            mrow[half] = mnew[half];
        }
        #pragma unroll
        for (int j = 0; j < 8; j++) {
            o[j][0] *= alpha[0]; o[j][1] *= alpha[0];
            o[j][2] *= alpha[1]; o[j][3] *= alpha[1];
        }

        const uint32_t vbase = smem_to_u32(Vb);
        #pragma unroll
        for (int kk = 0; kk < 4; kk++) {
            uint32_t pa[4] = {
                h2u(__floats2half2_rn(sv[2 * kk][0],     sv[2 * kk][1])),
                h2u(__floats2half2_rn(sv[2 * kk][2],     sv[2 * kk][3])),
                h2u(__floats2half2_rn(sv[2 * kk + 1][0], sv[2 * kk + 1][1])),
                h2u(__floats2half2_rn(sv[2 * kk + 1][2], sv[2 * kk + 1][3]))
            };
            #pragma unroll
            for (int jp = 0; jp < 4; jp++) {
                uint32_t vb[4];
                uint32_t addr = vbase + ((kk * 16 + vrow) * VPH + jp * 16 + vcol) * 2;
                LDSM4T(vb[0], vb[1], vb[2], vb[3], addr);
                mma1616(o[jp * 2],     pa, vb);
                mma1616(o[jp * 2 + 1], pa, vb + 2);
            }
        }
    }

    float linv[2] = {1.f / lrow[0], 1.f / lrow[1]};
    #pragma unroll
    for (int half = 0; half < 2; half++) {
        size_t row = (size_t)(b * T_ + qb + wq + lr + half * 8);
        __half* op = out + row * D_ + h * 64;
        #pragma unroll
        for (int j = 0; j < 8; j++)
            *(__half2*)(op + j * 8 + lc * 2) =
                __floats2half2_rn(o[j][half * 2] * linv[half], o[j][half * 2 + 1] * linv[half]);
    }
}

// ---------------- launch -----------------------------------------------------------
extern "C" void kernel_launch(void* const* d_in, const int* in_sizes, int n_in,
                              void* d_out, int out_size)
{
    const float* x      = (const float*)d_in[0];
    const int*   amask  = (const int*)d_in[1];
    const float* ln1_w  = (const float*)d_in[2];
    const float* ln1_b  = (const float*)d_in[3];
    const float* w_attn = (const float*)d_in[4];
    const float* b_attn = (const float*)d_in[5];
    const float* w_proj = (const float*)d_in[6];
    const float* b_proj = (const float*)d_in[7];
    const float* ln2_w  = (const float*)d_in[8];
    const float* ln2_b  = (const float*)d_in[9];
    const float* w_fc   = (const float*)d_in[10];
    const float* b_fc   = (const float*)d_in[11];
    const float* w_fcp  = (const float*)d_in[12];
    const float* b_fcp  = (const float*)d_in[13];
    float* out = (float*)d_out;

    __half *p_x1h, *p_qkvh, *p_attnh, *p_hh, *p_wah, *p_wph, *p_wfh, *p_wfph;
    float* p_x2;
    cudaGetSymbolAddress((void**)&p_x1h,   g_x1h);
    cudaGetSymbolAddress((void**)&p_qkvh,  g_qkvh);
    cudaGetSymbolAddress((void**)&p_attnh, g_attnh);
    cudaGetSymbolAddress((void**)&p_x2,    g_x2);
    cudaGetSymbolAddress((void**)&p_hh,    g_hh);
    cudaGetSymbolAddress((void**)&p_wah,   g_wah);
    cudaGetSymbolAddress((void**)&p_wph,   g_wph);
    cudaGetSymbolAddress((void**)&p_wfh,   g_wfh);
    cudaGetSymbolAddress((void**)&p_wfph,  g_wfph);

    cudaFuncSetAttribute(hgemm<EPI_BIAS, true>,       cudaFuncAttributeMaxDynamicSharedMemorySize, GEMM_SMEM);
    cudaFuncSetAttribute(hgemm<EPI_BIAS_RES, false>,  cudaFuncAttributeMaxDynamicSharedMemorySize, GEMM_SMEM);
    cudaFuncSetAttribute(hgemm<EPI_BIAS_GELU, true>,  cudaFuncAttributeMaxDynamicSharedMemorySize, GEMM_SMEM);
    cudaFuncSetAttribute(attn_h_kernel, cudaFuncAttributeMaxDynamicSharedMemorySize, ATTN_SMEM_BYTES);

    cvt_all<<<(N4_ALL + 255) / 256, 256>>>(
        (const float4*)w_attn, (const float4*)w_proj, (const float4*)w_fc, (const float4*)w_fcp,
        (__half2*)p_wah, (__half2*)p_wph, (__half2*)p_wfh, (__half2*)p_wfph);

    // 1) ln1 -> fp16
    ln_kernel<<<M_ / 8, 256>>>(x, ln1_w, ln1_b, p_x1h);
    // 2) qkv = x1 @ w_attn + b_attn
    hgemm<EPI_BIAS, true><<<dim3(2304 / 128, M_ / 128), 256, GEMM_SMEM>>>(
        p_x1h, p_wah, b_attn, nullptr, nullptr, p_qkvh, 2304, 768);
    // 3) attention (pipelined K/V)
    attn_h_kernel<<<dim3(T_ / TQ, H_, B_), 256, ATTN_SMEM_BYTES>>>(p_qkvh, amask, p_attnh);
    // 4) x2 = attn @ w_proj + b_proj + x
    hgemm<EPI_BIAS_RES, false><<<dim3(768 / 128, M_ / 128), 256, GEMM_SMEM>>>(
        p_attnh, p_wph, b_proj, x, p_x2, nullptr, 768, 768);
    // 5) ln2 -> fp16
    ln_kernel<<<M_ / 8, 256>>>(p_x2, ln2_w, ln2_b, p_x1h);
    // 6) h = gelu(x1 @ w_fc + b_fc)
    hgemm<EPI_BIAS_GELU, true><<<dim3(3072 / 128, M_ / 128), 256, GEMM_SMEM>>>(
        p_x1h, p_wfh, b_fc, nullptr, nullptr, p_hh, 3072, 768);
    // 7) out = h @ w_fc_proj + b_fc_proj + x2
    hgemm<EPI_BIAS_RES, false><<<dim3(768 / 128, M_ / 128), 256, GEMM_SMEM>>>(
        p_hh, p_wfph, b_fcp, p_x2, out, nullptr, 768, 3072);
}